// round 9
// baseline (speedup 1.0000x reference)
#include <cuda_runtime.h>
#include <cuda_fp16.h>
#include <cstdint>

#define NN 50000
#define NE 600000
#define F  128
#define NT 4
#define NOUT 640        // [self(128) | Y_t(128)*4]
#define RS 136          // padded smem row stride (fp16 elems)
#define HALF_N 64
#define NHALF 10        // NOUT / HALF_N

typedef unsigned long long ull;

// ---------------- scratch (static device globals; no allocation) ------------
__device__ float g_Y[(size_t)NN * NOUT];       // projected features per node
__device__ int   g_cnt[NT * NN];               // per-(type,dst) in-degree
__device__ int   g_off[NN];                    // exclusive CSR offsets (per dst)
__device__ int   g_cursor[NN];                 // fill cursors (end = off + deg)
__device__ int   g_epk[NE];                    // packed (src<<2)|type, bucketed by dst
__device__ int   g_bsum[64];                   // block sums for scan
__device__ __half g_Ahi[(size_t)NN * F];
__device__ __half g_Alo[(size_t)NN * F];
__device__ __half g_Whi1[NOUT * F];            // [n][k] layout (K-major rows)
__device__ __half g_Wlo1[NOUT * F];
__device__ __half g_Whi2[NOUT * F];
__device__ __half g_Wlo2[NOUT * F];
__device__ float g_bb1[F];
__device__ float g_bb2[F];

// ---------------- weight prep: fold type-mean, split to fp16 hi/lo ----------
__global__ void prep_weights(const float* __restrict__ Ws1, const float* __restrict__ Wn1,
                             const float* __restrict__ b1,
                             const float* __restrict__ Ws2, const float* __restrict__ Wn2,
                             const float* __restrict__ b2) {
    int idx = blockIdx.x * blockDim.x + threadIdx.x;   // over NOUT*F = 81920
    if (idx >= NOUT * F) return;
    int j = idx / F, k = idx % F;    // output col j, input k  (stored [j][k])
    float w1, w2;
    if (j < F) {
        float a1 = 0.f, a2 = 0.f;
        #pragma unroll
        for (int t = 0; t < NT; t++) {
            a1 += Ws1[(t * F + k) * F + j];
            a2 += Ws2[(t * F + k) * F + j];
        }
        w1 = a1 * 0.25f; w2 = a2 * 0.25f;
    } else {
        int t  = (j - F) >> 7;
        int jj = (j - F) & 127;
        w1 = Wn1[(t * F + k) * F + jj] * 0.25f;
        w2 = Wn2[(t * F + k) * F + jj] * 0.25f;
    }
    __half h1 = __float2half_rn(w1);
    __half h2 = __float2half_rn(w2);
    g_Whi1[idx] = h1; g_Wlo1[idx] = __float2half_rn(w1 - __half2float(h1));
    g_Whi2[idx] = h2; g_Wlo2[idx] = __float2half_rn(w2 - __half2float(h2));
    if (idx < F) {
        float s1 = 0.f, s2 = 0.f;
        #pragma unroll
        for (int t = 0; t < NT; t++) { s1 += b1[t * F + idx]; s2 += b2[t * F + idx]; }
        g_bb1[idx] = s1 * 0.25f; g_bb2[idx] = s2 * 0.25f;
    }
}

// ---------------- fp32 -> fp16 hi/lo conversion (x only) ---------------------
__global__ void convert_f16(const float* __restrict__ A) {
    size_t i = ((size_t)blockIdx.x * 256 + threadIdx.x) * 8;
    if (i >= (size_t)NN * F) return;
    float4 u0 = *reinterpret_cast<const float4*>(A + i);
    float4 u1 = *reinterpret_cast<const float4*>(A + i + 4);
    float f[8] = {u0.x, u0.y, u0.z, u0.w, u1.x, u1.y, u1.z, u1.w};
    uint32_t hw[4], lw[4];
    #pragma unroll
    for (int j = 0; j < 4; j++) {
        float a = f[2 * j], b = f[2 * j + 1];
        __half ha = __float2half_rn(a);
        __half hb = __float2half_rn(b);
        __half2 hp = __halves2half2(ha, hb);
        __half2 lp = __floats2half2_rn(a - __half2float(ha), b - __half2float(hb));
        hw[j] = *reinterpret_cast<uint32_t*>(&hp);
        lw[j] = *reinterpret_cast<uint32_t*>(&lp);
    }
    *reinterpret_cast<uint4*>(g_Ahi + i) = make_uint4(hw[0], hw[1], hw[2], hw[3]);
    *reinterpret_cast<uint4*>(g_Alo + i) = make_uint4(lw[0], lw[1], lw[2], lw[3]);
}

// ---------------- CSR build ---------------------------------------------------
__global__ void zero_cnt() {
    int i = blockIdx.x * blockDim.x + threadIdx.x;
    if (i < NT * NN) g_cnt[i] = 0;
}
__global__ void count_edges(const int* __restrict__ ei, const int* __restrict__ et) {
    int e = blockIdx.x * blockDim.x + threadIdx.x;
    if (e >= NE) return;
    atomicAdd(&g_cnt[et[e] * NN + ei[NE + e]], 1);
}

__global__ void scan_blocks() {
    __shared__ int wsum[32];
    int tid = threadIdx.x, lane = tid & 31, w = tid >> 5;
    int idx = blockIdx.x * 1024 + tid;
    int v = 0;
    if (idx < NN) {
        #pragma unroll
        for (int t = 0; t < NT; t++) v += g_cnt[t * NN + idx];
    }
    int x = v;
    #pragma unroll
    for (int o = 1; o < 32; o <<= 1) {
        int y = __shfl_up_sync(0xFFFFFFFFu, x, o);
        if (lane >= o) x += y;
    }
    if (lane == 31) wsum[w] = x;
    __syncthreads();
    if (w == 0) {
        int s = wsum[lane];
        #pragma unroll
        for (int o = 1; o < 32; o <<= 1) {
            int y = __shfl_up_sync(0xFFFFFFFFu, s, o);
            if (lane >= o) s += y;
        }
        wsum[lane] = s;
    }
    __syncthreads();
    int excl = x - v + (w > 0 ? wsum[w - 1] : 0);
    if (idx < NN) g_off[idx] = excl;
    if (tid == 0) g_bsum[blockIdx.x] = wsum[31];
}
__global__ void scan_bsums() {
    __shared__ int s[64];
    int tid = threadIdx.x;
    s[tid] = (tid < 49) ? g_bsum[tid] : 0;
    __syncthreads();
    #pragma unroll
    for (int o = 1; o < 64; o <<= 1) {
        int v = (tid >= o) ? s[tid - o] : 0;
        __syncthreads();
        s[tid] += v;
        __syncthreads();
    }
    if (tid < 49) g_bsum[tid] = (tid > 0) ? s[tid - 1] : 0;
}
__global__ void add_bsums() {
    int idx = blockIdx.x * 1024 + threadIdx.x;
    if (idx < NN) {
        int o = g_off[idx] + g_bsum[blockIdx.x];
        g_off[idx] = o;
        g_cursor[idx] = o;
    }
}

__global__ void fill_edges(const int* __restrict__ ei, const int* __restrict__ et) {
    int e = blockIdx.x * blockDim.x + threadIdx.x;
    if (e >= NE) return;
    int src = ei[e];
    int dst = ei[NE + e];
    int t = et[e];
    int pos = atomicAdd(&g_cursor[dst], 1);
    g_epk[pos] = (src << 2) | t;
}

// ---------------- mma.sync fp16 GEMM: Y[N,640] = A[N,128] @ W[128,640] --------
// One CTA per 128-row M tile. A (hi/lo) resident; B streamed in 64-col halves,
// single buffer (102KB smem -> 2 CTAs/SM).
// Split: hh = Ahi*Bhi (f32 acc); mix = Ahi*Blo + Alo*Bhi (f16 acc, packed).
__device__ __forceinline__ void mma_f32acc(float* d, const uint32_t* a, const uint32_t* b) {
    asm volatile("mma.sync.aligned.m16n8k16.row.col.f32.f16.f16.f32 "
                 "{%0,%1,%2,%3}, {%4,%5,%6,%7}, {%8,%9}, {%0,%1,%2,%3};"
                 : "+f"(d[0]), "+f"(d[1]), "+f"(d[2]), "+f"(d[3])
                 : "r"(a[0]), "r"(a[1]), "r"(a[2]), "r"(a[3]),
                   "r"(b[0]), "r"(b[1]));
}
__device__ __forceinline__ void mma_f16acc(uint32_t* d, const uint32_t* a, const uint32_t* b) {
    asm volatile("mma.sync.aligned.m16n8k16.row.col.f16.f16.f16.f16 "
                 "{%0,%1}, {%2,%3,%4,%5}, {%6,%7}, {%0,%1};"
                 : "+r"(d[0]), "+r"(d[1])
                 : "r"(a[0]), "r"(a[1]), "r"(a[2]), "r"(a[3]),
                   "r"(b[0]), "r"(b[1]));
}
__device__ __forceinline__ void ldsm_x4(uint32_t* r, uint32_t saddr) {
    asm volatile("ldmatrix.sync.aligned.m8n8.x4.shared.b16 {%0,%1,%2,%3}, [%4];"
                 : "=r"(r[0]), "=r"(r[1]), "=r"(r[2]), "=r"(r[3]) : "r"(saddr));
}
__device__ __forceinline__ void cp16(void* dst, const void* src) {
    uint32_t d = (uint32_t)__cvta_generic_to_shared(dst);
    asm volatile("cp.async.cg.shared.global [%0], [%1], 16;" :: "r"(d), "l"(src));
}
#define CP_COMMIT() asm volatile("cp.async.commit_group;" ::: "memory")
#define CP_WAIT0()  asm volatile("cp.async.wait_group 0;" ::: "memory")

__global__ __launch_bounds__(256, 2)
void gemm_tc(const __half* __restrict__ whi, const __half* __restrict__ wlo,
             const float* __restrict__ bias, float* __restrict__ Y) {
    extern __shared__ __half smem[];
    __half* Ahi = smem;                              // 128 x RS
    __half* Alo = Ahi + 128 * RS;                    // 128 x RS
    __half* Bh  = Alo + 128 * RS;                    // 64 x RS (hi)
    __half* Bl  = Bh + HALF_N * RS;                  // 64 x RS (lo)

    int tid = threadIdx.x, wid = tid >> 5, lane = tid & 31;
    int gid = lane >> 2, tig = lane & 3;
    int l8 = lane & 7, sel = lane >> 3;
    int wm = wid & 3, wn = wid >> 2;                 // warp tile rows wm*32, cols wn*32
    int m0 = blockIdx.x * 128;

    // --- resident A tile (hi/lo), loaded once via cp.async ---
    {
        bool full = (m0 + 128 <= NN);
        #pragma unroll
        for (int i = 0; i < 8; i++) {
            int lin = tid + i * 256;                 // 0..2047
            int r = lin >> 4, c = lin & 15;
            int gr = m0 + r;
            if (full || gr < NN) {
                cp16(Ahi + r * RS + c * 8, g_Ahi + (size_t)gr * F + c * 8);
                cp16(Alo + r * RS + c * 8, g_Alo + (size_t)gr * F + c * 8);
            } else {
                *reinterpret_cast<uint4*>(Ahi + r * RS + c * 8) = make_uint4(0, 0, 0, 0);
                *reinterpret_cast<uint4*>(Alo + r * RS + c * 8) = make_uint4(0, 0, 0, 0);
            }
        }
    }
    // --- B half-tile prefetch (single buffer) ---
    auto issue_B = [&](int s) {
        const __half* srch = whi + (size_t)s * HALF_N * F;
        const __half* srcl = wlo + (size_t)s * HALF_N * F;
        #pragma unroll
        for (int i = 0; i < 4; i++) {
            int lin = tid + i * 256;                 // 0..1023
            int r = lin >> 4, c = lin & 15;
            cp16(Bh + r * RS + c * 8, srch + r * F + c * 8);
            cp16(Bl + r * RS + c * 8, srcl + r * F + c * 8);
        }
        CP_COMMIT();
    };
    issue_B(0);

    uint32_t sAhi = (uint32_t)__cvta_generic_to_shared(Ahi);
    uint32_t sAlo = (uint32_t)__cvta_generic_to_shared(Alo);
    uint32_t sBh  = (uint32_t)__cvta_generic_to_shared(Bh);
    uint32_t sBl  = (uint32_t)__cvta_generic_to_shared(Bl);

    int a_r = (sel & 1) * 8 + l8;
    int a_k = (sel >> 1) * 8;
    int b_n = (sel >> 1) * 8 + l8;
    int b_k = (sel & 1) * 8;

    for (int s = 0; s < NHALF; s++) {
        CP_WAIT0();
        __syncthreads();                              // B(s) visible to all warps

        float    ahh[2][4][4];
        uint32_t amx[2][4][2];                        // f16x2-packed mix accumulators
        #pragma unroll
        for (int i = 0; i < 2; i++)
            #pragma unroll
            for (int j = 0; j < 4; j++) {
                #pragma unroll
                for (int q = 0; q < 4; q++) ahh[i][j][q] = 0.f;
                amx[i][j][0] = 0u; amx[i][j][1] = 0u;
            }

        #pragma unroll
        for (int ks = 0; ks < 8; ks++) {
            int kb = ks * 16;
            uint32_t ah[2][4], al[2][4];
            #pragma unroll
            for (int mf = 0; mf < 2; mf++) {
                uint32_t off = (uint32_t)(((wm * 32 + mf * 16 + a_r) * RS + kb + a_k) * 2);
                ldsm_x4(ah[mf], sAhi + off);
                ldsm_x4(al[mf], sAlo + off);
            }
            uint32_t bh[2][4], bl[2][4];
            #pragma unroll
            for (int g = 0; g < 2; g++) {
                uint32_t off = (uint32_t)(((wn * 32 + g * 16 + b_n) * RS + kb + b_k) * 2);
                ldsm_x4(bh[g], sBh + off);
                ldsm_x4(bl[g], sBl + off);
            }
            #pragma unroll
            for (int mf = 0; mf < 2; mf++)
                #pragma unroll
                for (int g = 0; g < 2; g++) {
                    mma_f32acc(ahh[mf][g * 2],     ah[mf], &bh[g][0]);   // hh (f32 acc)
                    mma_f32acc(ahh[mf][g * 2 + 1], ah[mf], &bh[g][2]);
                    mma_f16acc(amx[mf][g * 2],     ah[mf], &bl[g][0]);   // mix (f16 acc)
                    mma_f16acc(amx[mf][g * 2 + 1], ah[mf], &bl[g][2]);
                    mma_f16acc(amx[mf][g * 2],     al[mf], &bh[g][0]);
                    mma_f16acc(amx[mf][g * 2 + 1], al[mf], &bh[g][2]);
                }
        }
        __syncthreads();                              // all warps done reading B(s)
        if (s + 1 < NHALF) issue_B(s + 1);            // async; overlaps epilogue

        // epilogue for this 64-col half: global cols s*64 .. s*64+63
        int gc0 = s * HALF_N;
        bool has_bias = (gc0 < F);
        #pragma unroll
        for (int nf = 0; nf < 4; nf++) {
            int gc = gc0 + wn * 32 + nf * 8 + tig * 2;
            float b0 = has_bias ? bias[gc]     : 0.f;
            float b1 = has_bias ? bias[gc + 1] : 0.f;
            #pragma unroll
            for (int mf = 0; mf < 2; mf++) {
                float2 mx0 = __half22float2(*reinterpret_cast<__half2*>(&amx[mf][nf][0]));
                float2 mx1 = __half22float2(*reinterpret_cast<__half2*>(&amx[mf][nf][1]));
                int row = m0 + wm * 32 + mf * 16 + gid;
                float* base = Y + (size_t)row * NOUT + gc;
                if (row < NN)
                    *reinterpret_cast<float2*>(base) =
                        make_float2(ahh[mf][nf][0] + mx0.x + b0,
                                    ahh[mf][nf][1] + mx0.y + b1);
                if (row + 8 < NN)
                    *reinterpret_cast<float2*>(base + 8 * NOUT) =
                        make_float2(ahh[mf][nf][2] + mx1.x + b0,
                                    ahh[mf][nf][3] + mx1.y + b1);
            }
        }
    }
}

// ---------------- aggregate: out[dst] = Yself[dst] + sum_e invc[t]*Yt[src] ----
// NORM=true: l2norm+relu, then write fp16 hi/lo (layer-2 GEMM input) directly.
template <bool NORM>
__global__ void aggregate(float* __restrict__ outp) {
    int gtid = blockIdx.x * blockDim.x + threadIdx.x;
    int row = gtid >> 5;
    int lane = threadIdx.x & 31;
    if (row >= NN) return;

    float inv[NT];
    #pragma unroll
    for (int t = 0; t < NT; t++) {
        int c = __ldg(&g_cnt[t * NN + row]);
        inv[t] = 1.0f / (float)(c > 1 ? c : 1);
    }
    int beg = g_off[row];
    int end = g_cursor[row];

    float4 acc = *reinterpret_cast<const float4*>(g_Y + (size_t)row * NOUT + lane * 4);

    int i = beg;
    for (; i + 4 <= end; i += 4) {
        int pk0 = __ldg(&g_epk[i]);
        int pk1 = __ldg(&g_epk[i + 1]);
        int pk2 = __ldg(&g_epk[i + 2]);
        int pk3 = __ldg(&g_epk[i + 3]);
        const float4 v0 = *reinterpret_cast<const float4*>(
            g_Y + (size_t)(pk0 >> 2) * NOUT + ((pk0 & 3) + 1) * F + lane * 4);
        const float4 v1 = *reinterpret_cast<const float4*>(
            g_Y + (size_t)(pk1 >> 2) * NOUT + ((pk1 & 3) + 1) * F + lane * 4);
        const float4 v2 = *reinterpret_cast<const float4*>(
            g_Y + (size_t)(pk2 >> 2) * NOUT + ((pk2 & 3) + 1) * F + lane * 4);
        const float4 v3 = *reinterpret_cast<const float4*>(
            g_Y + (size_t)(pk3 >> 2) * NOUT + ((pk3 & 3) + 1) * F + lane * 4);
        float s0 = inv[pk0 & 3], s1 = inv[pk1 & 3], s2 = inv[pk2 & 3], s3 = inv[pk3 & 3];
        acc.x += s0 * v0.x; acc.y += s0 * v0.y; acc.z += s0 * v0.z; acc.w += s0 * v0.w;
        acc.x += s1 * v1.x; acc.y += s1 * v1.y; acc.z += s1 * v1.z; acc.w += s1 * v1.w;
        acc.x += s2 * v2.x; acc.y += s2 * v2.y; acc.z += s2 * v2.z; acc.w += s2 * v2.w;
        acc.x += s3 * v3.x; acc.y += s3 * v3.y; acc.z += s3 * v3.z; acc.w += s3 * v3.w;
    }
    for (; i < end; i++) {
        int pk = __ldg(&g_epk[i]);
        const float4 v = *reinterpret_cast<const float4*>(
            g_Y + (size_t)(pk >> 2) * NOUT + ((pk & 3) + 1) * F + lane * 4);
        float s = inv[pk & 3];
        acc.x += s * v.x; acc.y += s * v.y; acc.z += s * v.z; acc.w += s * v.w;
    }

    if (NORM) {
        float ss = acc.x * acc.x + acc.y * acc.y + acc.z * acc.z + acc.w * acc.w;
        #pragma unroll
        for (int o = 16; o > 0; o >>= 1)
            ss += __shfl_xor_sync(0xFFFFFFFFu, ss, o);
        float invn = 1.0f / fmaxf(sqrtf(ss), 1e-12f);
        acc.x = fmaxf(acc.x * invn, 0.f);
        acc.y = fmaxf(acc.y * invn, 0.f);
        acc.z = fmaxf(acc.z * invn, 0.f);
        acc.w = fmaxf(acc.w * invn, 0.f);
        float f[4] = {acc.x, acc.y, acc.z, acc.w};
        uint32_t hw[2], lw[2];
        #pragma unroll
        for (int j = 0; j < 2; j++) {
            float a = f[2 * j], b = f[2 * j + 1];
            __half ha = __float2half_rn(a);
            __half hb = __float2half_rn(b);
            __half2 hp = __halves2half2(ha, hb);
            __half2 lp = __floats2half2_rn(a - __half2float(ha), b - __half2float(hb));
            hw[j] = *reinterpret_cast<uint32_t*>(&hp);
            lw[j] = *reinterpret_cast<uint32_t*>(&lp);
        }
        size_t o = (size_t)row * F + lane * 4;
        *reinterpret_cast<uint2*>(g_Ahi + o) = make_uint2(hw[0], hw[1]);
        *reinterpret_cast<uint2*>(g_Alo + o) = make_uint2(lw[0], lw[1]);
    } else {
        *(reinterpret_cast<float4*>(outp + (size_t)row * F) + lane) = acc;
    }
}

// ---------------- launch -------------------------------------------------------
extern "C" void kernel_launch(void* const* d_in, const int* in_sizes, int n_in,
                              void* d_out, int out_size) {
    const float* x   = (const float*)d_in[0];
    const float* Ws1 = (const float*)d_in[1];
    const float* Wn1 = (const float*)d_in[2];
    const float* b1  = (const float*)d_in[3];
    const float* Ws2 = (const float*)d_in[4];
    const float* Wn2 = (const float*)d_in[5];
    const float* b2  = (const float*)d_in[6];
    const int*   ei  = (const int*)d_in[7];
    const int*   et  = (const int*)d_in[8];
    float* out = (float*)d_out;

    void *p_Y, *p_bb1, *p_bb2, *p_Whi1, *p_Wlo1, *p_Whi2, *p_Wlo2;
    cudaGetSymbolAddress(&p_Y, g_Y);
    cudaGetSymbolAddress(&p_bb1, g_bb1);
    cudaGetSymbolAddress(&p_bb2, g_bb2);
    cudaGetSymbolAddress(&p_Whi1, g_Whi1);
    cudaGetSymbolAddress(&p_Wlo1, g_Wlo1);
    cudaGetSymbolAddress(&p_Whi2, g_Whi2);
    cudaGetSymbolAddress(&p_Wlo2, g_Wlo2);

    // smem: A hi/lo (2*128*RS) + B single-buffered hi/lo half (2*64*RS) = 102KB
    const int SMEM_GEMM = (2 * 128 * RS + 2 * HALF_N * RS) * (int)sizeof(__half);
    cudaFuncSetAttribute(gemm_tc, cudaFuncAttributeMaxDynamicSharedMemorySize, SMEM_GEMM);

    const int GM_BLOCKS = (NN + 127) / 128;         // 391
    const int AG_BLOCKS = (int)(((size_t)NN * 32 + 255) / 256);
    const int SCAN_BLOCKS = (NN + 1023) / 1024;     // 49
    const int CV_BLOCKS = (int)(((size_t)NN * F / 8 + 255) / 256);

    prep_weights<<<(NOUT * F + 255) / 256, 256>>>(Ws1, Wn1, b1, Ws2, Wn2, b2);  // 1
    convert_f16<<<CV_BLOCKS, 256>>>(x);                                         // 2
    zero_cnt<<<(NT * NN + 255) / 256, 256>>>();                                 // 3
    gemm_tc<<<GM_BLOCKS, 256, SMEM_GEMM>>>((const __half*)p_Whi1,               // 4 <- profiled
                                           (const __half*)p_Wlo1,
                                           (const float*)p_bb1, (float*)p_Y);
    count_edges<<<(NE + 255) / 256, 256>>>(ei, et);                             // 5
    scan_blocks<<<SCAN_BLOCKS, 1024>>>();                                       // 6
    scan_bsums<<<1, 64>>>();                                                    // 7
    add_bsums<<<SCAN_BLOCKS, 1024>>>();                                         // 8
    fill_edges<<<(NE + 255) / 256, 256>>>(ei, et);                              // 9
    aggregate<true><<<AG_BLOCKS, 256>>>(nullptr);                               // 10 (writes Ahi/Alo)

    // ---- layer 2 ----
    gemm_tc<<<GM_BLOCKS, 256, SMEM_GEMM>>>((const __half*)p_Whi2,               // 11
                                           (const __half*)p_Wlo2,
                                           (const float*)p_bb2, (float*)p_Y);
    aggregate<false><<<AG_BLOCKS, 256>>>(out);                                  // 12
}

// round 10
// speedup vs baseline: 1.3642x; 1.3642x over previous
#include <cuda_runtime.h>
#include <cuda_fp16.h>
#include <cstdint>

#define NN 50000
#define NE 600000
#define F  128
#define NT 4
#define NOUT 640        // [self(128) | Y_t(128)*4]
#define RS 136          // padded smem row stride (fp16 elems)
#define HALF_N 64
#define NHALF 10        // NOUT / HALF_N

typedef unsigned long long ull;

// ---------------- scratch (static device globals; no allocation) ------------
__device__ float g_Y[(size_t)NN * NOUT];       // projected features per node
__device__ int   g_cnt[NT * NN];               // per-(type,dst) in-degree
__device__ int   g_off[NN];                    // exclusive CSR offsets (per dst)
__device__ int   g_cursor[NN];                 // fill cursors (end = off + deg)
__device__ int   g_epk[NE];                    // packed (src<<2)|type, bucketed by dst
__device__ int   g_bsum[64];                   // block sums for scan
__device__ __half g_Ah[(size_t)NN * F];        // fp16 activations
__device__ __half g_W1[NOUT * F];              // [n][k] layout (K-major rows)
__device__ __half g_W2[NOUT * F];
__device__ float g_bb1[F];
__device__ float g_bb2[F];

// ---------------- weight prep: fold type-mean, round to fp16 ----------------
__global__ void prep_weights(const float* __restrict__ Ws1, const float* __restrict__ Wn1,
                             const float* __restrict__ b1,
                             const float* __restrict__ Ws2, const float* __restrict__ Wn2,
                             const float* __restrict__ b2) {
    int idx = blockIdx.x * blockDim.x + threadIdx.x;   // over NOUT*F = 81920
    if (idx >= NOUT * F) return;
    int j = idx / F, k = idx % F;    // output col j, input k  (stored [j][k])
    float w1, w2;
    if (j < F) {
        float a1 = 0.f, a2 = 0.f;
        #pragma unroll
        for (int t = 0; t < NT; t++) {
            a1 += Ws1[(t * F + k) * F + j];
            a2 += Ws2[(t * F + k) * F + j];
        }
        w1 = a1 * 0.25f; w2 = a2 * 0.25f;
    } else {
        int t  = (j - F) >> 7;
        int jj = (j - F) & 127;
        w1 = Wn1[(t * F + k) * F + jj] * 0.25f;
        w2 = Wn2[(t * F + k) * F + jj] * 0.25f;
    }
    g_W1[idx] = __float2half_rn(w1);
    g_W2[idx] = __float2half_rn(w2);
    if (idx < F) {
        float s1 = 0.f, s2 = 0.f;
        #pragma unroll
        for (int t = 0; t < NT; t++) { s1 += b1[t * F + idx]; s2 += b2[t * F + idx]; }
        g_bb1[idx] = s1 * 0.25f; g_bb2[idx] = s2 * 0.25f;
    }
}

// ---------------- fp32 -> fp16 conversion (x only) ---------------------------
__global__ void convert_f16(const float* __restrict__ A) {
    size_t i = ((size_t)blockIdx.x * 256 + threadIdx.x) * 8;
    if (i >= (size_t)NN * F) return;
    float4 u0 = *reinterpret_cast<const float4*>(A + i);
    float4 u1 = *reinterpret_cast<const float4*>(A + i + 4);
    __half2 h0 = __floats2half2_rn(u0.x, u0.y);
    __half2 h1 = __floats2half2_rn(u0.z, u0.w);
    __half2 h2 = __floats2half2_rn(u1.x, u1.y);
    __half2 h3 = __floats2half2_rn(u1.z, u1.w);
    *reinterpret_cast<uint4*>(g_Ah + i) =
        make_uint4(*reinterpret_cast<uint32_t*>(&h0), *reinterpret_cast<uint32_t*>(&h1),
                   *reinterpret_cast<uint32_t*>(&h2), *reinterpret_cast<uint32_t*>(&h3));
}

// ---------------- CSR build ---------------------------------------------------
__global__ void zero_cnt() {
    int i = blockIdx.x * blockDim.x + threadIdx.x;
    if (i < NT * NN) g_cnt[i] = 0;
}
__global__ void count_edges(const int* __restrict__ ei, const int* __restrict__ et) {
    int e = blockIdx.x * blockDim.x + threadIdx.x;
    if (e >= NE) return;
    atomicAdd(&g_cnt[et[e] * NN + ei[NE + e]], 1);
}

__global__ void scan_blocks() {
    __shared__ int wsum[32];
    int tid = threadIdx.x, lane = tid & 31, w = tid >> 5;
    int idx = blockIdx.x * 1024 + tid;
    int v = 0;
    if (idx < NN) {
        #pragma unroll
        for (int t = 0; t < NT; t++) v += g_cnt[t * NN + idx];
    }
    int x = v;
    #pragma unroll
    for (int o = 1; o < 32; o <<= 1) {
        int y = __shfl_up_sync(0xFFFFFFFFu, x, o);
        if (lane >= o) x += y;
    }
    if (lane == 31) wsum[w] = x;
    __syncthreads();
    if (w == 0) {
        int s = wsum[lane];
        #pragma unroll
        for (int o = 1; o < 32; o <<= 1) {
            int y = __shfl_up_sync(0xFFFFFFFFu, s, o);
            if (lane >= o) s += y;
        }
        wsum[lane] = s;
    }
    __syncthreads();
    int excl = x - v + (w > 0 ? wsum[w - 1] : 0);
    if (idx < NN) g_off[idx] = excl;
    if (tid == 0) g_bsum[blockIdx.x] = wsum[31];
}
__global__ void scan_bsums() {
    __shared__ int s[64];
    int tid = threadIdx.x;
    s[tid] = (tid < 49) ? g_bsum[tid] : 0;
    __syncthreads();
    #pragma unroll
    for (int o = 1; o < 64; o <<= 1) {
        int v = (tid >= o) ? s[tid - o] : 0;
        __syncthreads();
        s[tid] += v;
        __syncthreads();
    }
    if (tid < 49) g_bsum[tid] = (tid > 0) ? s[tid - 1] : 0;
}
__global__ void add_bsums() {
    int idx = blockIdx.x * 1024 + threadIdx.x;
    if (idx < NN) {
        int o = g_off[idx] + g_bsum[blockIdx.x];
        g_off[idx] = o;
        g_cursor[idx] = o;
    }
}

__global__ void fill_edges(const int* __restrict__ ei, const int* __restrict__ et) {
    int e = blockIdx.x * blockDim.x + threadIdx.x;
    if (e >= NE) return;
    int src = ei[e];
    int dst = ei[NE + e];
    int t = et[e];
    int pos = atomicAdd(&g_cursor[dst], 1);
    g_epk[pos] = (src << 2) | t;
}

// ---------------- mma.sync fp16 GEMM: Y[N,640] = A[N,128] @ W[128,640] --------
// Single pass fp16 x fp16 -> f32. One CTA per 128-row M tile; A resident;
// B streamed in 64-col halves (single buffer). smem 51KB -> 3 CTAs/SM.
__device__ __forceinline__ void mma_f32acc(float* d, const uint32_t* a, const uint32_t* b) {
    asm volatile("mma.sync.aligned.m16n8k16.row.col.f32.f16.f16.f32 "
                 "{%0,%1,%2,%3}, {%4,%5,%6,%7}, {%8,%9}, {%0,%1,%2,%3};"
                 : "+f"(d[0]), "+f"(d[1]), "+f"(d[2]), "+f"(d[3])
                 : "r"(a[0]), "r"(a[1]), "r"(a[2]), "r"(a[3]),
                   "r"(b[0]), "r"(b[1]));
}
__device__ __forceinline__ void ldsm_x4(uint32_t* r, uint32_t saddr) {
    asm volatile("ldmatrix.sync.aligned.m8n8.x4.shared.b16 {%0,%1,%2,%3}, [%4];"
                 : "=r"(r[0]), "=r"(r[1]), "=r"(r[2]), "=r"(r[3]) : "r"(saddr));
}
__device__ __forceinline__ void cp16(void* dst, const void* src) {
    uint32_t d = (uint32_t)__cvta_generic_to_shared(dst);
    asm volatile("cp.async.cg.shared.global [%0], [%1], 16;" :: "r"(d), "l"(src));
}
#define CP_COMMIT() asm volatile("cp.async.commit_group;" ::: "memory")
#define CP_WAIT0()  asm volatile("cp.async.wait_group 0;" ::: "memory")

__global__ __launch_bounds__(256, 3)
void gemm_tc(const __half* __restrict__ wmat,
             const float* __restrict__ bias, float* __restrict__ Y) {
    extern __shared__ __half smem[];
    __half* As = smem;                               // 128 x RS
    __half* Bs = As + 128 * RS;                      // 64 x RS

    int tid = threadIdx.x, wid = tid >> 5, lane = tid & 31;
    int gid = lane >> 2, tig = lane & 3;
    int l8 = lane & 7, sel = lane >> 3;
    int wm = wid & 3, wn = wid >> 2;                 // warp tile rows wm*32, cols wn*32
    int m0 = blockIdx.x * 128;

    // --- resident A tile, loaded once via cp.async ---
    {
        bool full = (m0 + 128 <= NN);
        #pragma unroll
        for (int i = 0; i < 8; i++) {
            int lin = tid + i * 256;                 // 0..2047
            int r = lin >> 4, c = lin & 15;
            int gr = m0 + r;
            if (full || gr < NN)
                cp16(As + r * RS + c * 8, g_Ah + (size_t)gr * F + c * 8);
            else
                *reinterpret_cast<uint4*>(As + r * RS + c * 8) = make_uint4(0, 0, 0, 0);
        }
    }
    // --- B half-tile prefetch (single buffer) ---
    auto issue_B = [&](int s) {
        const __half* src = wmat + (size_t)s * HALF_N * F;
        #pragma unroll
        for (int i = 0; i < 4; i++) {
            int lin = tid + i * 256;                 // 0..1023
            int r = lin >> 4, c = lin & 15;
            if (r < HALF_N) cp16(Bs + r * RS + c * 8, src + r * F + c * 8);
        }
        CP_COMMIT();
    };
    issue_B(0);

    uint32_t sA = (uint32_t)__cvta_generic_to_shared(As);
    uint32_t sB = (uint32_t)__cvta_generic_to_shared(Bs);

    int a_r = (sel & 1) * 8 + l8;
    int a_k = (sel >> 1) * 8;
    int b_n = (sel >> 1) * 8 + l8;
    int b_k = (sel & 1) * 8;

    for (int s = 0; s < NHALF; s++) {
        CP_WAIT0();
        __syncthreads();                              // B(s) visible to all warps

        float acc[2][4][4];
        #pragma unroll
        for (int i = 0; i < 2; i++)
            #pragma unroll
            for (int j = 0; j < 4; j++)
                #pragma unroll
                for (int q = 0; q < 4; q++) acc[i][j][q] = 0.f;

        #pragma unroll
        for (int ks = 0; ks < 8; ks++) {
            int kb = ks * 16;
            uint32_t af[2][4];
            #pragma unroll
            for (int mf = 0; mf < 2; mf++) {
                uint32_t off = (uint32_t)(((wm * 32 + mf * 16 + a_r) * RS + kb + a_k) * 2);
                ldsm_x4(af[mf], sA + off);
            }
            uint32_t bf[2][4];
            #pragma unroll
            for (int g = 0; g < 2; g++) {
                uint32_t off = (uint32_t)(((wn * 32 + g * 16 + b_n) * RS + kb + b_k) * 2);
                ldsm_x4(bf[g], sB + off);
            }
            #pragma unroll
            for (int mf = 0; mf < 2; mf++)
                #pragma unroll
                for (int g = 0; g < 2; g++) {
                    mma_f32acc(acc[mf][g * 2],     af[mf], &bf[g][0]);
                    mma_f32acc(acc[mf][g * 2 + 1], af[mf], &bf[g][2]);
                }
        }
        __syncthreads();                              // all warps done reading B(s)
        if (s + 1 < NHALF) issue_B(s + 1);            // async; overlaps epilogue

        // epilogue for this 64-col half: global cols s*64 .. s*64+63
        int gc0 = s * HALF_N;
        bool has_bias = (gc0 < F);
        #pragma unroll
        for (int nf = 0; nf < 4; nf++) {
            int gc = gc0 + wn * 32 + nf * 8 + tig * 2;
            float b0 = has_bias ? bias[gc]     : 0.f;
            float b1 = has_bias ? bias[gc + 1] : 0.f;
            #pragma unroll
            for (int mf = 0; mf < 2; mf++) {
                int row = m0 + wm * 32 + mf * 16 + gid;
                float* base = Y + (size_t)row * NOUT + gc;
                if (row < NN)
                    *reinterpret_cast<float2*>(base) =
                        make_float2(acc[mf][nf][0] + b0, acc[mf][nf][1] + b1);
                if (row + 8 < NN)
                    *reinterpret_cast<float2*>(base + 8 * NOUT) =
                        make_float2(acc[mf][nf][2] + b0, acc[mf][nf][3] + b1);
            }
        }
    }
}

// ---------------- aggregate: out[dst] = Yself[dst] + sum_e invc[t]*Yt[src] ----
// NORM=true: l2norm+relu, then write fp16 (layer-2 GEMM input) directly.
template <bool NORM>
__global__ void aggregate(float* __restrict__ outp) {
    int gtid = blockIdx.x * blockDim.x + threadIdx.x;
    int row = gtid >> 5;
    int lane = threadIdx.x & 31;
    if (row >= NN) return;

    float inv[NT];
    #pragma unroll
    for (int t = 0; t < NT; t++) {
        int c = __ldg(&g_cnt[t * NN + row]);
        inv[t] = 1.0f / (float)(c > 1 ? c : 1);
    }
    int beg = g_off[row];
    int end = g_cursor[row];

    float4 acc = *reinterpret_cast<const float4*>(g_Y + (size_t)row * NOUT + lane * 4);

    int i = beg;
    for (; i + 4 <= end; i += 4) {
        int pk0 = __ldg(&g_epk[i]);
        int pk1 = __ldg(&g_epk[i + 1]);
        int pk2 = __ldg(&g_epk[i + 2]);
        int pk3 = __ldg(&g_epk[i + 3]);
        const float4 v0 = *reinterpret_cast<const float4*>(
            g_Y + (size_t)(pk0 >> 2) * NOUT + ((pk0 & 3) + 1) * F + lane * 4);
        const float4 v1 = *reinterpret_cast<const float4*>(
            g_Y + (size_t)(pk1 >> 2) * NOUT + ((pk1 & 3) + 1) * F + lane * 4);
        const float4 v2 = *reinterpret_cast<const float4*>(
            g_Y + (size_t)(pk2 >> 2) * NOUT + ((pk2 & 3) + 1) * F + lane * 4);
        const float4 v3 = *reinterpret_cast<const float4*>(
            g_Y + (size_t)(pk3 >> 2) * NOUT + ((pk3 & 3) + 1) * F + lane * 4);
        float s0 = inv[pk0 & 3], s1 = inv[pk1 & 3], s2 = inv[pk2 & 3], s3 = inv[pk3 & 3];
        acc.x += s0 * v0.x; acc.y += s0 * v0.y; acc.z += s0 * v0.z; acc.w += s0 * v0.w;
        acc.x += s1 * v1.x; acc.y += s1 * v1.y; acc.z += s1 * v1.z; acc.w += s1 * v1.w;
        acc.x += s2 * v2.x; acc.y += s2 * v2.y; acc.z += s2 * v2.z; acc.w += s2 * v2.w;
        acc.x += s3 * v3.x; acc.y += s3 * v3.y; acc.z += s3 * v3.z; acc.w += s3 * v3.w;
    }
    for (; i < end; i++) {
        int pk = __ldg(&g_epk[i]);
        const float4 v = *reinterpret_cast<const float4*>(
            g_Y + (size_t)(pk >> 2) * NOUT + ((pk & 3) + 1) * F + lane * 4);
        float s = inv[pk & 3];
        acc.x += s * v.x; acc.y += s * v.y; acc.z += s * v.z; acc.w += s * v.w;
    }

    if (NORM) {
        float ss = acc.x * acc.x + acc.y * acc.y + acc.z * acc.z + acc.w * acc.w;
        #pragma unroll
        for (int o = 16; o > 0; o >>= 1)
            ss += __shfl_xor_sync(0xFFFFFFFFu, ss, o);
        float invn = 1.0f / fmaxf(sqrtf(ss), 1e-12f);
        acc.x = fmaxf(acc.x * invn, 0.f);
        acc.y = fmaxf(acc.y * invn, 0.f);
        acc.z = fmaxf(acc.z * invn, 0.f);
        acc.w = fmaxf(acc.w * invn, 0.f);
        __half2 h0 = __floats2half2_rn(acc.x, acc.y);
        __half2 h1 = __floats2half2_rn(acc.z, acc.w);
        size_t o = (size_t)row * F + lane * 4;
        *reinterpret_cast<uint2*>(g_Ah + o) =
            make_uint2(*reinterpret_cast<uint32_t*>(&h0), *reinterpret_cast<uint32_t*>(&h1));
    } else {
        *(reinterpret_cast<float4*>(outp + (size_t)row * F) + lane) = acc;
    }
}

// ---------------- launch -------------------------------------------------------
extern "C" void kernel_launch(void* const* d_in, const int* in_sizes, int n_in,
                              void* d_out, int out_size) {
    const float* x   = (const float*)d_in[0];
    const float* Ws1 = (const float*)d_in[1];
    const float* Wn1 = (const float*)d_in[2];
    const float* b1  = (const float*)d_in[3];
    const float* Ws2 = (const float*)d_in[4];
    const float* Wn2 = (const float*)d_in[5];
    const float* b2  = (const float*)d_in[6];
    const int*   ei  = (const int*)d_in[7];
    const int*   et  = (const int*)d_in[8];
    float* out = (float*)d_out;

    void *p_Y, *p_bb1, *p_bb2, *p_W1, *p_W2;
    cudaGetSymbolAddress(&p_Y, g_Y);
    cudaGetSymbolAddress(&p_bb1, g_bb1);
    cudaGetSymbolAddress(&p_bb2, g_bb2);
    cudaGetSymbolAddress(&p_W1, g_W1);
    cudaGetSymbolAddress(&p_W2, g_W2);

    // smem: A (128*RS) + B single-buffered half (64*RS) = 51KB -> 3 CTAs/SM
    const int SMEM_GEMM = (128 * RS + HALF_N * RS) * (int)sizeof(__half);
    cudaFuncSetAttribute(gemm_tc, cudaFuncAttributeMaxDynamicSharedMemorySize, SMEM_GEMM);

    const int GM_BLOCKS = (NN + 127) / 128;         // 391
    const int AG_BLOCKS = (int)(((size_t)NN * 32 + 255) / 256);
    const int SCAN_BLOCKS = (NN + 1023) / 1024;     // 49
    const int CV_BLOCKS = (int)(((size_t)NN * F / 8 + 255) / 256);

    prep_weights<<<(NOUT * F + 255) / 256, 256>>>(Ws1, Wn1, b1, Ws2, Wn2, b2);  // 1
    convert_f16<<<CV_BLOCKS, 256>>>(x);                                         // 2
    zero_cnt<<<(NT * NN + 255) / 256, 256>>>();                                 // 3
    gemm_tc<<<GM_BLOCKS, 256, SMEM_GEMM>>>((const __half*)p_W1,                 // 4 <- profiled
                                           (const float*)p_bb1, (float*)p_Y);
    count_edges<<<(NE + 255) / 256, 256>>>(ei, et);                             // 5
    scan_blocks<<<SCAN_BLOCKS, 1024>>>();                                       // 6
    scan_bsums<<<1, 64>>>();                                                    // 7
    add_bsums<<<SCAN_BLOCKS, 1024>>>();                                         // 8
    fill_edges<<<(NE + 255) / 256, 256>>>(ei, et);                              // 9
    aggregate<true><<<AG_BLOCKS, 256>>>(nullptr);                               // 10 (writes g_Ah fp16)

    // ---- layer 2 ----
    gemm_tc<<<GM_BLOCKS, 256, SMEM_GEMM>>>((const __half*)p_W2,                 // 11
                                           (const float*)p_bb2, (float*)p_Y);
    aggregate<false><<<AG_BLOCKS, 256>>>(out);                                  // 12
}

// round 11
// speedup vs baseline: 1.5463x; 1.1335x over previous
#include <cuda_runtime.h>
#include <cuda_fp16.h>
#include <cstdint>

#define NN 50000
#define NE 600000
#define F  128
#define NT 4
#define NOUT 640        // [self(128) | Y_t(128)*4]
#define RS 136          // padded smem row stride (fp16 elems)
#define HALF_N 64
#define NHALF 10        // NOUT / HALF_N

typedef unsigned long long ull;

// ---------------- scratch (static device globals; no allocation) ------------
__device__ __half g_Y[(size_t)NN * NOUT];      // projected features (fp16)
__device__ int   g_cnt[NT * NN];               // per-(type,dst) in-degree
__device__ int   g_off[NN];                    // exclusive CSR offsets (per dst)
__device__ int   g_cursor[NN];                 // fill cursors (end = off + deg)
__device__ int   g_epk[NE];                    // packed (src<<2)|type, bucketed by dst
__device__ int   g_bsum[64];                   // block sums for scan
__device__ __half g_Ah[(size_t)NN * F];        // fp16 activations
__device__ __half g_W1[NOUT * F];              // [n][k] layout (K-major rows)
__device__ __half g_W2[NOUT * F];
__device__ float g_bb1[F];
__device__ float g_bb2[F];

// ---------------- weight prep: fold type-mean, round to fp16 ----------------
__global__ void prep_weights(const float* __restrict__ Ws1, const float* __restrict__ Wn1,
                             const float* __restrict__ b1,
                             const float* __restrict__ Ws2, const float* __restrict__ Wn2,
                             const float* __restrict__ b2) {
    int idx = blockIdx.x * blockDim.x + threadIdx.x;   // over NOUT*F = 81920
    if (idx >= NOUT * F) return;
    int j = idx / F, k = idx % F;    // output col j, input k  (stored [j][k])
    float w1, w2;
    if (j < F) {
        float a1 = 0.f, a2 = 0.f;
        #pragma unroll
        for (int t = 0; t < NT; t++) {
            a1 += Ws1[(t * F + k) * F + j];
            a2 += Ws2[(t * F + k) * F + j];
        }
        w1 = a1 * 0.25f; w2 = a2 * 0.25f;
    } else {
        int t  = (j - F) >> 7;
        int jj = (j - F) & 127;
        w1 = Wn1[(t * F + k) * F + jj] * 0.25f;
        w2 = Wn2[(t * F + k) * F + jj] * 0.25f;
    }
    g_W1[idx] = __float2half_rn(w1);
    g_W2[idx] = __float2half_rn(w2);
    if (idx < F) {
        float s1 = 0.f, s2 = 0.f;
        #pragma unroll
        for (int t = 0; t < NT; t++) { s1 += b1[t * F + idx]; s2 += b2[t * F + idx]; }
        g_bb1[idx] = s1 * 0.25f; g_bb2[idx] = s2 * 0.25f;
    }
}

// ---------------- fp32 -> fp16 conversion (x only) ---------------------------
__global__ void convert_f16(const float* __restrict__ A) {
    size_t i = ((size_t)blockIdx.x * 256 + threadIdx.x) * 8;
    if (i >= (size_t)NN * F) return;
    float4 u0 = *reinterpret_cast<const float4*>(A + i);
    float4 u1 = *reinterpret_cast<const float4*>(A + i + 4);
    __half2 h0 = __floats2half2_rn(u0.x, u0.y);
    __half2 h1 = __floats2half2_rn(u0.z, u0.w);
    __half2 h2 = __floats2half2_rn(u1.x, u1.y);
    __half2 h3 = __floats2half2_rn(u1.z, u1.w);
    *reinterpret_cast<uint4*>(g_Ah + i) =
        make_uint4(*reinterpret_cast<uint32_t*>(&h0), *reinterpret_cast<uint32_t*>(&h1),
                   *reinterpret_cast<uint32_t*>(&h2), *reinterpret_cast<uint32_t*>(&h3));
}

// ---------------- CSR build ---------------------------------------------------
__global__ void zero_cnt() {
    int i = blockIdx.x * blockDim.x + threadIdx.x;
    if (i < NT * NN) g_cnt[i] = 0;
}
__global__ void count_edges(const int* __restrict__ ei, const int* __restrict__ et) {
    int e = blockIdx.x * blockDim.x + threadIdx.x;
    if (e >= NE) return;
    atomicAdd(&g_cnt[et[e] * NN + ei[NE + e]], 1);
}

__global__ void scan_blocks() {
    __shared__ int wsum[32];
    int tid = threadIdx.x, lane = tid & 31, w = tid >> 5;
    int idx = blockIdx.x * 1024 + tid;
    int v = 0;
    if (idx < NN) {
        #pragma unroll
        for (int t = 0; t < NT; t++) v += g_cnt[t * NN + idx];
    }
    int x = v;
    #pragma unroll
    for (int o = 1; o < 32; o <<= 1) {
        int y = __shfl_up_sync(0xFFFFFFFFu, x, o);
        if (lane >= o) x += y;
    }
    if (lane == 31) wsum[w] = x;
    __syncthreads();
    if (w == 0) {
        int s = wsum[lane];
        #pragma unroll
        for (int o = 1; o < 32; o <<= 1) {
            int y = __shfl_up_sync(0xFFFFFFFFu, s, o);
            if (lane >= o) s += y;
        }
        wsum[lane] = s;
    }
    __syncthreads();
    int excl = x - v + (w > 0 ? wsum[w - 1] : 0);
    if (idx < NN) g_off[idx] = excl;
    if (tid == 0) g_bsum[blockIdx.x] = wsum[31];
}
__global__ void scan_bsums() {
    __shared__ int s[64];
    int tid = threadIdx.x;
    s[tid] = (tid < 49) ? g_bsum[tid] : 0;
    __syncthreads();
    #pragma unroll
    for (int o = 1; o < 64; o <<= 1) {
        int v = (tid >= o) ? s[tid - o] : 0;
        __syncthreads();
        s[tid] += v;
        __syncthreads();
    }
    if (tid < 49) g_bsum[tid] = (tid > 0) ? s[tid - 1] : 0;
}
__global__ void add_bsums() {
    int idx = blockIdx.x * 1024 + threadIdx.x;
    if (idx < NN) {
        int o = g_off[idx] + g_bsum[blockIdx.x];
        g_off[idx] = o;
        g_cursor[idx] = o;
    }
}

__global__ void fill_edges(const int* __restrict__ ei, const int* __restrict__ et) {
    int e = blockIdx.x * blockDim.x + threadIdx.x;
    if (e >= NE) return;
    int src = ei[e];
    int dst = ei[NE + e];
    int t = et[e];
    int pos = atomicAdd(&g_cursor[dst], 1);
    g_epk[pos] = (src << 2) | t;
}

// ---------------- mma.sync fp16 GEMM: Y[N,640] = A[N,128] @ W[128,640] --------
// Single pass fp16 x fp16 -> f32 accum, fp16 store. One CTA per 128-row M tile;
// A resident; B streamed in 64-col halves (single buffer). smem 51KB, 3 CTA/SM.
__device__ __forceinline__ void mma_f32acc(float* d, const uint32_t* a, const uint32_t* b) {
    asm volatile("mma.sync.aligned.m16n8k16.row.col.f32.f16.f16.f32 "
                 "{%0,%1,%2,%3}, {%4,%5,%6,%7}, {%8,%9}, {%0,%1,%2,%3};"
                 : "+f"(d[0]), "+f"(d[1]), "+f"(d[2]), "+f"(d[3])
                 : "r"(a[0]), "r"(a[1]), "r"(a[2]), "r"(a[3]),
                   "r"(b[0]), "r"(b[1]));
}
__device__ __forceinline__ void ldsm_x4(uint32_t* r, uint32_t saddr) {
    asm volatile("ldmatrix.sync.aligned.m8n8.x4.shared.b16 {%0,%1,%2,%3}, [%4];"
                 : "=r"(r[0]), "=r"(r[1]), "=r"(r[2]), "=r"(r[3]) : "r"(saddr));
}
__device__ __forceinline__ void cp16(void* dst, const void* src) {
    uint32_t d = (uint32_t)__cvta_generic_to_shared(dst);
    asm volatile("cp.async.cg.shared.global [%0], [%1], 16;" :: "r"(d), "l"(src));
}
#define CP_COMMIT() asm volatile("cp.async.commit_group;" ::: "memory")
#define CP_WAIT0()  asm volatile("cp.async.wait_group 0;" ::: "memory")

__global__ __launch_bounds__(256, 3)
void gemm_tc(const __half* __restrict__ wmat,
             const float* __restrict__ bias, __half* __restrict__ Y) {
    extern __shared__ __half smem[];
    __half* As = smem;                               // 128 x RS
    __half* Bs = As + 128 * RS;                      // 64 x RS

    int tid = threadIdx.x, wid = tid >> 5, lane = tid & 31;
    int gid = lane >> 2, tig = lane & 3;
    int l8 = lane & 7, sel = lane >> 3;
    int wm = wid & 3, wn = wid >> 2;                 // warp tile rows wm*32, cols wn*32
    int m0 = blockIdx.x * 128;

    // --- resident A tile, loaded once via cp.async ---
    {
        bool full = (m0 + 128 <= NN);
        #pragma unroll
        for (int i = 0; i < 8; i++) {
            int lin = tid + i * 256;                 // 0..2047
            int r = lin >> 4, c = lin & 15;
            int gr = m0 + r;
            if (full || gr < NN)
                cp16(As + r * RS + c * 8, g_Ah + (size_t)gr * F + c * 8);
            else
                *reinterpret_cast<uint4*>(As + r * RS + c * 8) = make_uint4(0, 0, 0, 0);
        }
    }
    // --- B half-tile prefetch (single buffer) ---
    auto issue_B = [&](int s) {
        const __half* src = wmat + (size_t)s * HALF_N * F;
        #pragma unroll
        for (int i = 0; i < 4; i++) {
            int lin = tid + i * 256;                 // 0..1023
            int r = lin >> 4, c = lin & 15;
            cp16(Bs + r * RS + c * 8, src + r * F + c * 8);
        }
        CP_COMMIT();
    };
    issue_B(0);

    uint32_t sA = (uint32_t)__cvta_generic_to_shared(As);
    uint32_t sB = (uint32_t)__cvta_generic_to_shared(Bs);

    int a_r = (sel & 1) * 8 + l8;
    int a_k = (sel >> 1) * 8;
    int b_n = (sel >> 1) * 8 + l8;
    int b_k = (sel & 1) * 8;

    for (int s = 0; s < NHALF; s++) {
        CP_WAIT0();
        __syncthreads();                              // B(s) visible to all warps

        float acc[2][4][4];
        #pragma unroll
        for (int i = 0; i < 2; i++)
            #pragma unroll
            for (int j = 0; j < 4; j++)
                #pragma unroll
                for (int q = 0; q < 4; q++) acc[i][j][q] = 0.f;

        #pragma unroll
        for (int ks = 0; ks < 8; ks++) {
            int kb = ks * 16;
            uint32_t af[2][4];
            #pragma unroll
            for (int mf = 0; mf < 2; mf++) {
                uint32_t off = (uint32_t)(((wm * 32 + mf * 16 + a_r) * RS + kb + a_k) * 2);
                ldsm_x4(af[mf], sA + off);
            }
            uint32_t bf[2][4];
            #pragma unroll
            for (int g = 0; g < 2; g++) {
                uint32_t off = (uint32_t)(((wn * 32 + g * 16 + b_n) * RS + kb + b_k) * 2);
                ldsm_x4(bf[g], sB + off);
            }
            #pragma unroll
            for (int mf = 0; mf < 2; mf++)
                #pragma unroll
                for (int g = 0; g < 2; g++) {
                    mma_f32acc(acc[mf][g * 2],     af[mf], &bf[g][0]);
                    mma_f32acc(acc[mf][g * 2 + 1], af[mf], &bf[g][2]);
                }
        }
        __syncthreads();                              // all warps done reading B(s)
        if (s + 1 < NHALF) issue_B(s + 1);            // async; overlaps epilogue

        // epilogue for this 64-col half: global cols s*64 .. s*64+63, fp16 store
        int gc0 = s * HALF_N;
        bool has_bias = (gc0 < F);
        #pragma unroll
        for (int nf = 0; nf < 4; nf++) {
            int gc = gc0 + wn * 32 + nf * 8 + tig * 2;
            float b0 = has_bias ? bias[gc]     : 0.f;
            float b1 = has_bias ? bias[gc + 1] : 0.f;
            #pragma unroll
            for (int mf = 0; mf < 2; mf++) {
                int row = m0 + wm * 32 + mf * 16 + gid;
                __half* base = Y + (size_t)row * NOUT + gc;
                if (row < NN) {
                    __half2 p = __floats2half2_rn(acc[mf][nf][0] + b0, acc[mf][nf][1] + b1);
                    *reinterpret_cast<uint32_t*>(base) = *reinterpret_cast<uint32_t*>(&p);
                }
                if (row + 8 < NN) {
                    __half2 p = __floats2half2_rn(acc[mf][nf][2] + b0, acc[mf][nf][3] + b1);
                    *reinterpret_cast<uint32_t*>(base + 8 * NOUT) = *reinterpret_cast<uint32_t*>(&p);
                }
            }
        }
    }
}

// ---------------- aggregate: out[dst] = Yself[dst] + sum_e invc[t]*Yt[src] ----
// Y is fp16; accumulation in fp32. NORM=true: l2norm+relu -> fp16 g_Ah.
__device__ __forceinline__ float4 ld_y4(const __half* p) {
    uint2 u = *reinterpret_cast<const uint2*>(p);
    float2 a = __half22float2(*reinterpret_cast<__half2*>(&u.x));
    float2 b = __half22float2(*reinterpret_cast<__half2*>(&u.y));
    return make_float4(a.x, a.y, b.x, b.y);
}

template <bool NORM>
__global__ void aggregate(float* __restrict__ outp) {
    int gtid = blockIdx.x * blockDim.x + threadIdx.x;
    int row = gtid >> 5;
    int lane = threadIdx.x & 31;
    if (row >= NN) return;

    float inv[NT];
    #pragma unroll
    for (int t = 0; t < NT; t++) {
        int c = __ldg(&g_cnt[t * NN + row]);
        inv[t] = 1.0f / (float)(c > 1 ? c : 1);
    }
    int beg = g_off[row];
    int end = g_cursor[row];

    float4 acc = ld_y4(g_Y + (size_t)row * NOUT + lane * 4);

    int i = beg;
    for (; i + 4 <= end; i += 4) {
        int pk0 = __ldg(&g_epk[i]);
        int pk1 = __ldg(&g_epk[i + 1]);
        int pk2 = __ldg(&g_epk[i + 2]);
        int pk3 = __ldg(&g_epk[i + 3]);
        float4 v0 = ld_y4(g_Y + (size_t)(pk0 >> 2) * NOUT + ((pk0 & 3) + 1) * F + lane * 4);
        float4 v1 = ld_y4(g_Y + (size_t)(pk1 >> 2) * NOUT + ((pk1 & 3) + 1) * F + lane * 4);
        float4 v2 = ld_y4(g_Y + (size_t)(pk2 >> 2) * NOUT + ((pk2 & 3) + 1) * F + lane * 4);
        float4 v3 = ld_y4(g_Y + (size_t)(pk3 >> 2) * NOUT + ((pk3 & 3) + 1) * F + lane * 4);
        float s0 = inv[pk0 & 3], s1 = inv[pk1 & 3], s2 = inv[pk2 & 3], s3 = inv[pk3 & 3];
        acc.x += s0 * v0.x; acc.y += s0 * v0.y; acc.z += s0 * v0.z; acc.w += s0 * v0.w;
        acc.x += s1 * v1.x; acc.y += s1 * v1.y; acc.z += s1 * v1.z; acc.w += s1 * v1.w;
        acc.x += s2 * v2.x; acc.y += s2 * v2.y; acc.z += s2 * v2.z; acc.w += s2 * v2.w;
        acc.x += s3 * v3.x; acc.y += s3 * v3.y; acc.z += s3 * v3.z; acc.w += s3 * v3.w;
    }
    for (; i < end; i++) {
        int pk = __ldg(&g_epk[i]);
        float4 v = ld_y4(g_Y + (size_t)(pk >> 2) * NOUT + ((pk & 3) + 1) * F + lane * 4);
        float s = inv[pk & 3];
        acc.x += s * v.x; acc.y += s * v.y; acc.z += s * v.z; acc.w += s * v.w;
    }

    if (NORM) {
        float ss = acc.x * acc.x + acc.y * acc.y + acc.z * acc.z + acc.w * acc.w;
        #pragma unroll
        for (int o = 16; o > 0; o >>= 1)
            ss += __shfl_xor_sync(0xFFFFFFFFu, ss, o);
        float invn = 1.0f / fmaxf(sqrtf(ss), 1e-12f);
        acc.x = fmaxf(acc.x * invn, 0.f);
        acc.y = fmaxf(acc.y * invn, 0.f);
        acc.z = fmaxf(acc.z * invn, 0.f);
        acc.w = fmaxf(acc.w * invn, 0.f);
        __half2 h0 = __floats2half2_rn(acc.x, acc.y);
        __half2 h1 = __floats2half2_rn(acc.z, acc.w);
        size_t o = (size_t)row * F + lane * 4;
        *reinterpret_cast<uint2*>(g_Ah + o) =
            make_uint2(*reinterpret_cast<uint32_t*>(&h0), *reinterpret_cast<uint32_t*>(&h1));
    } else {
        *(reinterpret_cast<float4*>(outp + (size_t)row * F) + lane) = acc;
    }
}

// ---------------- launch -------------------------------------------------------
extern "C" void kernel_launch(void* const* d_in, const int* in_sizes, int n_in,
                              void* d_out, int out_size) {
    const float* x   = (const float*)d_in[0];
    const float* Ws1 = (const float*)d_in[1];
    const float* Wn1 = (const float*)d_in[2];
    const float* b1  = (const float*)d_in[3];
    const float* Ws2 = (const float*)d_in[4];
    const float* Wn2 = (const float*)d_in[5];
    const float* b2  = (const float*)d_in[6];
    const int*   ei  = (const int*)d_in[7];
    const int*   et  = (const int*)d_in[8];
    float* out = (float*)d_out;

    void *p_Y, *p_bb1, *p_bb2, *p_W1, *p_W2;
    cudaGetSymbolAddress(&p_Y, g_Y);
    cudaGetSymbolAddress(&p_bb1, g_bb1);
    cudaGetSymbolAddress(&p_bb2, g_bb2);
    cudaGetSymbolAddress(&p_W1, g_W1);
    cudaGetSymbolAddress(&p_W2, g_W2);

    // smem: A (128*RS) + B single-buffered half (64*RS) = 51KB -> 3 CTAs/SM
    const int SMEM_GEMM = (128 * RS + HALF_N * RS) * (int)sizeof(__half);
    cudaFuncSetAttribute(gemm_tc, cudaFuncAttributeMaxDynamicSharedMemorySize, SMEM_GEMM);

    const int GM_BLOCKS = (NN + 127) / 128;         // 391
    const int AG_BLOCKS = (int)(((size_t)NN * 32 + 255) / 256);
    const int SCAN_BLOCKS = (NN + 1023) / 1024;     // 49
    const int CV_BLOCKS = (int)(((size_t)NN * F / 8 + 255) / 256);

    prep_weights<<<(NOUT * F + 255) / 256, 256>>>(Ws1, Wn1, b1, Ws2, Wn2, b2);  // 1
    convert_f16<<<CV_BLOCKS, 256>>>(x);                                         // 2
    zero_cnt<<<(NT * NN + 255) / 256, 256>>>();                                 // 3
    gemm_tc<<<GM_BLOCKS, 256, SMEM_GEMM>>>((const __half*)p_W1,                 // 4 <- profiled
                                           (const float*)p_bb1, (__half*)p_Y);
    count_edges<<<(NE + 255) / 256, 256>>>(ei, et);                             // 5
    scan_blocks<<<SCAN_BLOCKS, 1024>>>();                                       // 6
    scan_bsums<<<1, 64>>>();                                                    // 7
    add_bsums<<<SCAN_BLOCKS, 1024>>>();                                         // 8
    fill_edges<<<(NE + 255) / 256, 256>>>(ei, et);                              // 9
    aggregate<true><<<AG_BLOCKS, 256>>>(nullptr);                               // 10 (writes g_Ah fp16)

    // ---- layer 2 ----
    gemm_tc<<<GM_BLOCKS, 256, SMEM_GEMM>>>((const __half*)p_W2,                 // 11
                                           (const float*)p_bb2, (__half*)p_Y);
    aggregate<false><<<AG_BLOCKS, 256>>>(out);                                  // 12
}

// round 12
// speedup vs baseline: 1.6143x; 1.0440x over previous
#include <cuda_runtime.h>
#include <cuda_fp16.h>
#include <cstdint>

#define NN 50000
#define NE 600000
#define F  128
#define NT 4
#define NOUT 640        // [self(128) | Y_t(128)*4]
#define RS 136          // padded smem row stride (fp16 elems)
#define HALF_N 64
#define NHALF 10        // NOUT / HALF_N

typedef unsigned long long ull;

// ---------------- scratch (static device globals; no allocation) ------------
__device__ __half g_Y[(size_t)NN * NOUT];      // projected features (fp16)
__device__ int   g_cnt[NT * NN];               // per-(type,dst) in-degree
__device__ int   g_off[NN];                    // exclusive CSR offsets (per dst)
__device__ int   g_cursor[NN];                 // fill cursors (end = off + deg)
__device__ int   g_epk[NE];                    // packed (src<<2)|type, bucketed by dst
__device__ int   g_bsum[64];                   // block sums for scan
__device__ __half g_Ah[(size_t)NN * F];        // fp16 activations
__device__ __half g_W1[NOUT * F];              // [n][k] layout (K-major rows)
__device__ __half g_W2[NOUT * F];
__device__ float g_bb1[F];
__device__ float g_bb2[F];

// ---------------- weight prep: fold type-mean, round to fp16 ----------------
__global__ void prep_weights(const float* __restrict__ Ws1, const float* __restrict__ Wn1,
                             const float* __restrict__ b1,
                             const float* __restrict__ Ws2, const float* __restrict__ Wn2,
                             const float* __restrict__ b2) {
    int idx = blockIdx.x * blockDim.x + threadIdx.x;   // over NOUT*F = 81920
    if (idx >= NOUT * F) return;
    int j = idx / F, k = idx % F;    // output col j, input k  (stored [j][k])
    float w1, w2;
    if (j < F) {
        float a1 = 0.f, a2 = 0.f;
        #pragma unroll
        for (int t = 0; t < NT; t++) {
            a1 += Ws1[(t * F + k) * F + j];
            a2 += Ws2[(t * F + k) * F + j];
        }
        w1 = a1 * 0.25f; w2 = a2 * 0.25f;
    } else {
        int t  = (j - F) >> 7;
        int jj = (j - F) & 127;
        w1 = Wn1[(t * F + k) * F + jj] * 0.25f;
        w2 = Wn2[(t * F + k) * F + jj] * 0.25f;
    }
    g_W1[idx] = __float2half_rn(w1);
    g_W2[idx] = __float2half_rn(w2);
    if (idx < F) {
        float s1 = 0.f, s2 = 0.f;
        #pragma unroll
        for (int t = 0; t < NT; t++) { s1 += b1[t * F + idx]; s2 += b2[t * F + idx]; }
        g_bb1[idx] = s1 * 0.25f; g_bb2[idx] = s2 * 0.25f;
    }
}

// ---------------- fp32 -> fp16 conversion (x only) ---------------------------
__global__ void convert_f16(const float* __restrict__ A) {
    size_t i = ((size_t)blockIdx.x * 256 + threadIdx.x) * 8;
    if (i >= (size_t)NN * F) return;
    float4 u0 = *reinterpret_cast<const float4*>(A + i);
    float4 u1 = *reinterpret_cast<const float4*>(A + i + 4);
    __half2 h0 = __floats2half2_rn(u0.x, u0.y);
    __half2 h1 = __floats2half2_rn(u0.z, u0.w);
    __half2 h2 = __floats2half2_rn(u1.x, u1.y);
    __half2 h3 = __floats2half2_rn(u1.z, u1.w);
    *reinterpret_cast<uint4*>(g_Ah + i) =
        make_uint4(*reinterpret_cast<uint32_t*>(&h0), *reinterpret_cast<uint32_t*>(&h1),
                   *reinterpret_cast<uint32_t*>(&h2), *reinterpret_cast<uint32_t*>(&h3));
}

// ---------------- CSR build ---------------------------------------------------
__global__ void zero_cnt() {
    int i = blockIdx.x * blockDim.x + threadIdx.x;
    if (i < NT * NN) g_cnt[i] = 0;
}
__global__ void count_edges(const int* __restrict__ ei, const int* __restrict__ et) {
    int e = blockIdx.x * blockDim.x + threadIdx.x;
    if (e >= NE) return;
    atomicAdd(&g_cnt[et[e] * NN + ei[NE + e]], 1);
}

__global__ void scan_blocks() {
    __shared__ int wsum[32];
    int tid = threadIdx.x, lane = tid & 31, w = tid >> 5;
    int idx = blockIdx.x * 1024 + tid;
    int v = 0;
    if (idx < NN) {
        #pragma unroll
        for (int t = 0; t < NT; t++) v += g_cnt[t * NN + idx];
    }
    int x = v;
    #pragma unroll
    for (int o = 1; o < 32; o <<= 1) {
        int y = __shfl_up_sync(0xFFFFFFFFu, x, o);
        if (lane >= o) x += y;
    }
    if (lane == 31) wsum[w] = x;
    __syncthreads();
    if (w == 0) {
        int s = wsum[lane];
        #pragma unroll
        for (int o = 1; o < 32; o <<= 1) {
            int y = __shfl_up_sync(0xFFFFFFFFu, s, o);
            if (lane >= o) s += y;
        }
        wsum[lane] = s;
    }
    __syncthreads();
    int excl = x - v + (w > 0 ? wsum[w - 1] : 0);
    if (idx < NN) g_off[idx] = excl;
    if (tid == 0) g_bsum[blockIdx.x] = wsum[31];
}
__global__ void scan_bsums() {
    __shared__ int s[64];
    int tid = threadIdx.x;
    s[tid] = (tid < 49) ? g_bsum[tid] : 0;
    __syncthreads();
    #pragma unroll
    for (int o = 1; o < 64; o <<= 1) {
        int v = (tid >= o) ? s[tid - o] : 0;
        __syncthreads();
        s[tid] += v;
        __syncthreads();
    }
    if (tid < 49) g_bsum[tid] = (tid > 0) ? s[tid - 1] : 0;
}
__global__ void add_bsums() {
    int idx = blockIdx.x * 1024 + threadIdx.x;
    if (idx < NN) {
        int o = g_off[idx] + g_bsum[blockIdx.x];
        g_off[idx] = o;
        g_cursor[idx] = o;
    }
}

__global__ void fill_edges(const int* __restrict__ ei, const int* __restrict__ et) {
    int e = blockIdx.x * blockDim.x + threadIdx.x;
    if (e >= NE) return;
    int src = ei[e];
    int dst = ei[NE + e];
    int t = et[e];
    int pos = atomicAdd(&g_cursor[dst], 1);
    g_epk[pos] = (src << 2) | t;
}

// ---------------- mma.sync fp16 GEMM: Y[N,640] = A[N,128] @ W[128,640] --------
// fp16 x fp16 -> f32 accum, fp16 store. One CTA (128 threads, 4 warps) per
// 128-row M tile; A resident; B streamed in 64-col halves, double-buffered.
// Warp tile 64Mx32N: per k-step 4 A-ldsm + 2 B-ldsm feed 16 MMAs (192B/MMA).
// smem 69.6KB -> 3 CTAs/SM; grid 391 (0.88 wave).
__device__ __forceinline__ void mma_f32acc(float* d, const uint32_t* a, const uint32_t* b) {
    asm volatile("mma.sync.aligned.m16n8k16.row.col.f32.f16.f16.f32 "
                 "{%0,%1,%2,%3}, {%4,%5,%6,%7}, {%8,%9}, {%0,%1,%2,%3};"
                 : "+f"(d[0]), "+f"(d[1]), "+f"(d[2]), "+f"(d[3])
                 : "r"(a[0]), "r"(a[1]), "r"(a[2]), "r"(a[3]),
                   "r"(b[0]), "r"(b[1]));
}
__device__ __forceinline__ void ldsm_x4(uint32_t* r, uint32_t saddr) {
    asm volatile("ldmatrix.sync.aligned.m8n8.x4.shared.b16 {%0,%1,%2,%3}, [%4];"
                 : "=r"(r[0]), "=r"(r[1]), "=r"(r[2]), "=r"(r[3]) : "r"(saddr));
}
__device__ __forceinline__ void cp16(void* dst, const void* src) {
    uint32_t d = (uint32_t)__cvta_generic_to_shared(dst);
    asm volatile("cp.async.cg.shared.global [%0], [%1], 16;" :: "r"(d), "l"(src));
}
#define CP_COMMIT() asm volatile("cp.async.commit_group;" ::: "memory")
#define CP_WAIT(n)  asm volatile("cp.async.wait_group %0;" :: "n"(n) : "memory")

__global__ __launch_bounds__(128, 3)
void gemm_tc(const __half* __restrict__ wmat,
             const float* __restrict__ bias, __half* __restrict__ Y) {
    extern __shared__ __half smem[];
    __half* As   = smem;                             // 128 x RS
    __half* Bbuf = As + 128 * RS;                    // 2 x (64 x RS)

    int tid = threadIdx.x, wid = tid >> 5, lane = tid & 31;
    int gid = lane >> 2, tig = lane & 3;
    int l8 = lane & 7, sel = lane >> 3;
    int wm = wid & 1, wn = wid >> 1;                 // warp tile rows wm*64, cols wn*32
    int m0 = blockIdx.x * 128;

    // --- resident A tile, loaded once via cp.async (16 chunks/thread) ---
    {
        bool full = (m0 + 128 <= NN);
        #pragma unroll
        for (int i = 0; i < 16; i++) {
            int lin = tid + i * 128;                 // 0..2047
            int r = lin >> 4, c = lin & 15;
            int gr = m0 + r;
            if (full || gr < NN)
                cp16(As + r * RS + c * 8, g_Ah + (size_t)gr * F + c * 8);
            else
                *reinterpret_cast<uint4*>(As + r * RS + c * 8) = make_uint4(0, 0, 0, 0);
        }
    }
    // --- B half-tile prefetch into buffer buf ---
    auto issue_B = [&](int s, int buf) {
        const __half* src = wmat + (size_t)s * HALF_N * F;
        __half* dst = Bbuf + buf * HALF_N * RS;
        #pragma unroll
        for (int i = 0; i < 8; i++) {
            int lin = tid + i * 128;                 // 0..1023
            int r = lin >> 4, c = lin & 15;
            cp16(dst + r * RS + c * 8, src + r * F + c * 8);
        }
        CP_COMMIT();
    };
    issue_B(0, 0);

    uint32_t sA = (uint32_t)__cvta_generic_to_shared(As);

    int a_r = (sel & 1) * 8 + l8;
    int a_k = (sel >> 1) * 8;
    int b_n = (sel >> 1) * 8 + l8;
    int b_k = (sel & 1) * 8;

    for (int s = 0; s < NHALF; s++) {
        int buf = s & 1;
        if (s + 1 < NHALF) {
            issue_B(s + 1, buf ^ 1);
            CP_WAIT(1);
        } else {
            CP_WAIT(0);
        }
        __syncthreads();                              // B(s) + A visible

        uint32_t sB = (uint32_t)__cvta_generic_to_shared(Bbuf + buf * HALF_N * RS);

        float acc[4][4][4];
        #pragma unroll
        for (int i = 0; i < 4; i++)
            #pragma unroll
            for (int j = 0; j < 4; j++)
                #pragma unroll
                for (int q = 0; q < 4; q++) acc[i][j][q] = 0.f;

        #pragma unroll
        for (int ks = 0; ks < 8; ks++) {
            int kb = ks * 16;
            uint32_t af[4][4];
            #pragma unroll
            for (int mf = 0; mf < 4; mf++) {
                uint32_t off = (uint32_t)(((wm * 64 + mf * 16 + a_r) * RS + kb + a_k) * 2);
                ldsm_x4(af[mf], sA + off);
            }
            uint32_t bf[2][4];
            #pragma unroll
            for (int g = 0; g < 2; g++) {
                uint32_t off = (uint32_t)(((wn * 32 + g * 16 + b_n) * RS + kb + b_k) * 2);
                ldsm_x4(bf[g], sB + off);
            }
            #pragma unroll
            for (int mf = 0; mf < 4; mf++)
                #pragma unroll
                for (int g = 0; g < 2; g++) {
                    mma_f32acc(acc[mf][g * 2],     af[mf], &bf[g][0]);
                    mma_f32acc(acc[mf][g * 2 + 1], af[mf], &bf[g][2]);
                }
        }

        // epilogue for this 64-col half: global cols s*64 .. s*64+63, fp16 store
        int gc0 = s * HALF_N;
        bool has_bias = (gc0 < F);
        #pragma unroll
        for (int nf = 0; nf < 4; nf++) {
            int gc = gc0 + wn * 32 + nf * 8 + tig * 2;
            float b0 = has_bias ? bias[gc]     : 0.f;
            float b1 = has_bias ? bias[gc + 1] : 0.f;
            #pragma unroll
            for (int mf = 0; mf < 4; mf++) {
                int row = m0 + wm * 64 + mf * 16 + gid;
                __half* base = Y + (size_t)row * NOUT + gc;
                if (row < NN) {
                    __half2 p = __floats2half2_rn(acc[mf][nf][0] + b0, acc[mf][nf][1] + b1);
                    *reinterpret_cast<uint32_t*>(base) = *reinterpret_cast<uint32_t*>(&p);
                }
                if (row + 8 < NN) {
                    __half2 p = __floats2half2_rn(acc[mf][nf][2] + b0, acc[mf][nf][3] + b1);
                    *reinterpret_cast<uint32_t*>(base + 8 * NOUT) = *reinterpret_cast<uint32_t*>(&p);
                }
            }
        }
        __syncthreads();   // all warps done reading buf before it is refilled at s+2
    }
}

// ---------------- aggregate: out[dst] = Yself[dst] + sum_e invc[t]*Yt[src] ----
// Y is fp16; accumulation in fp32. NORM=true: l2norm+relu -> fp16 g_Ah.
__device__ __forceinline__ float4 ld_y4(const __half* p) {
    uint2 u = *reinterpret_cast<const uint2*>(p);
    float2 a = __half22float2(*reinterpret_cast<__half2*>(&u.x));
    float2 b = __half22float2(*reinterpret_cast<__half2*>(&u.y));
    return make_float4(a.x, a.y, b.x, b.y);
}

template <bool NORM>
__global__ void aggregate(float* __restrict__ outp) {
    int gtid = blockIdx.x * blockDim.x + threadIdx.x;
    int row = gtid >> 5;
    int lane = threadIdx.x & 31;
    if (row >= NN) return;

    float inv[NT];
    #pragma unroll
    for (int t = 0; t < NT; t++) {
        int c = __ldg(&g_cnt[t * NN + row]);
        inv[t] = 1.0f / (float)(c > 1 ? c : 1);
    }
    int beg = g_off[row];
    int end = g_cursor[row];

    float4 acc = ld_y4(g_Y + (size_t)row * NOUT + lane * 4);

    int i = beg;
    for (; i + 4 <= end; i += 4) {
        int pk0 = __ldg(&g_epk[i]);
        int pk1 = __ldg(&g_epk[i + 1]);
        int pk2 = __ldg(&g_epk[i + 2]);
        int pk3 = __ldg(&g_epk[i + 3]);
        float4 v0 = ld_y4(g_Y + (size_t)(pk0 >> 2) * NOUT + ((pk0 & 3) + 1) * F + lane * 4);
        float4 v1 = ld_y4(g_Y + (size_t)(pk1 >> 2) * NOUT + ((pk1 & 3) + 1) * F + lane * 4);
        float4 v2 = ld_y4(g_Y + (size_t)(pk2 >> 2) * NOUT + ((pk2 & 3) + 1) * F + lane * 4);
        float4 v3 = ld_y4(g_Y + (size_t)(pk3 >> 2) * NOUT + ((pk3 & 3) + 1) * F + lane * 4);
        float s0 = inv[pk0 & 3], s1 = inv[pk1 & 3], s2 = inv[pk2 & 3], s3 = inv[pk3 & 3];
        acc.x += s0 * v0.x; acc.y += s0 * v0.y; acc.z += s0 * v0.z; acc.w += s0 * v0.w;
        acc.x += s1 * v1.x; acc.y += s1 * v1.y; acc.z += s1 * v1.z; acc.w += s1 * v1.w;
        acc.x += s2 * v2.x; acc.y += s2 * v2.y; acc.z += s2 * v2.z; acc.w += s2 * v2.w;
        acc.x += s3 * v3.x; acc.y += s3 * v3.y; acc.z += s3 * v3.z; acc.w += s3 * v3.w;
    }
    for (; i < end; i++) {
        int pk = __ldg(&g_epk[i]);
        float4 v = ld_y4(g_Y + (size_t)(pk >> 2) * NOUT + ((pk & 3) + 1) * F + lane * 4);
        float s = inv[pk & 3];
        acc.x += s * v.x; acc.y += s * v.y; acc.z += s * v.z; acc.w += s * v.w;
    }

    if (NORM) {
        float ss = acc.x * acc.x + acc.y * acc.y + acc.z * acc.z + acc.w * acc.w;
        #pragma unroll
        for (int o = 16; o > 0; o >>= 1)
            ss += __shfl_xor_sync(0xFFFFFFFFu, ss, o);
        float invn = 1.0f / fmaxf(sqrtf(ss), 1e-12f);
        acc.x = fmaxf(acc.x * invn, 0.f);
        acc.y = fmaxf(acc.y * invn, 0.f);
        acc.z = fmaxf(acc.z * invn, 0.f);
        acc.w = fmaxf(acc.w * invn, 0.f);
        __half2 h0 = __floats2half2_rn(acc.x, acc.y);
        __half2 h1 = __floats2half2_rn(acc.z, acc.w);
        size_t o = (size_t)row * F + lane * 4;
        *reinterpret_cast<uint2*>(g_Ah + o) =
            make_uint2(*reinterpret_cast<uint32_t*>(&h0), *reinterpret_cast<uint32_t*>(&h1));
    } else {
        *(reinterpret_cast<float4*>(outp + (size_t)row * F) + lane) = acc;
    }
}

// ---------------- launch -------------------------------------------------------
extern "C" void kernel_launch(void* const* d_in, const int* in_sizes, int n_in,
                              void* d_out, int out_size) {
    const float* x   = (const float*)d_in[0];
    const float* Ws1 = (const float*)d_in[1];
    const float* Wn1 = (const float*)d_in[2];
    const float* b1  = (const float*)d_in[3];
    const float* Ws2 = (const float*)d_in[4];
    const float* Wn2 = (const float*)d_in[5];
    const float* b2  = (const float*)d_in[6];
    const int*   ei  = (const int*)d_in[7];
    const int*   et  = (const int*)d_in[8];
    float* out = (float*)d_out;

    void *p_Y, *p_bb1, *p_bb2, *p_W1, *p_W2;
    cudaGetSymbolAddress(&p_Y, g_Y);
    cudaGetSymbolAddress(&p_bb1, g_bb1);
    cudaGetSymbolAddress(&p_bb2, g_bb2);
    cudaGetSymbolAddress(&p_W1, g_W1);
    cudaGetSymbolAddress(&p_W2, g_W2);

    // smem: A (128*RS) + B double-buffered halves (2*64*RS) = 69.6KB -> 3 CTAs/SM
    const int SMEM_GEMM = (128 * RS + 2 * HALF_N * RS) * (int)sizeof(__half);
    cudaFuncSetAttribute(gemm_tc, cudaFuncAttributeMaxDynamicSharedMemorySize, SMEM_GEMM);

    const int GM_BLOCKS = (NN + 127) / 128;         // 391
    const int AG_BLOCKS = (int)(((size_t)NN * 32 + 255) / 256);
    const int SCAN_BLOCKS = (NN + 1023) / 1024;     // 49
    const int CV_BLOCKS = (int)(((size_t)NN * F / 8 + 255) / 256);

    prep_weights<<<(NOUT * F + 255) / 256, 256>>>(Ws1, Wn1, b1, Ws2, Wn2, b2);  // 1
    convert_f16<<<CV_BLOCKS, 256>>>(x);                                         // 2
    zero_cnt<<<(NT * NN + 255) / 256, 256>>>();                                 // 3
    gemm_tc<<<GM_BLOCKS, 128, SMEM_GEMM>>>((const __half*)p_W1,                 // 4 <- profiled
                                           (const float*)p_bb1, (__half*)p_Y);
    count_edges<<<(NE + 255) / 256, 256>>>(ei, et);                             // 5
    scan_blocks<<<SCAN_BLOCKS, 1024>>>();                                       // 6
    scan_bsums<<<1, 64>>>();                                                    // 7
    add_bsums<<<SCAN_BLOCKS, 1024>>>();                                         // 8
    fill_edges<<<(NE + 255) / 256, 256>>>(ei, et);                              // 9
    aggregate<true><<<AG_BLOCKS, 256>>>(nullptr);                               // 10 (writes g_Ah fp16)

    // ---- layer 2 ----
    gemm_tc<<<GM_BLOCKS, 128, SMEM_GEMM>>>((const __half*)p_W2,                 // 11
                                           (const float*)p_bb2, (__half*)p_Y);
    aggregate<false><<<AG_BLOCKS, 256>>>(out);                                  // 12
}

// round 13
// speedup vs baseline: 1.6935x; 1.0490x over previous
#include <cuda_runtime.h>
#include <cuda_fp16.h>
#include <cstdint>

#define NN 50000
#define NE 600000
#define F  128
#define NT 4
#define NOUT 640        // [self(128) | Y_t(128)*4]
#define RS 136          // padded smem row stride (fp16 elems)
#define HALF_N 64
#define NHALF 10        // NOUT / HALF_N

typedef unsigned long long ull;

// ---------------- scratch (static device globals; no allocation) ------------
__device__ __half g_Y[(size_t)NN * NOUT];      // projected features (fp16)
__device__ int   g_cnt[NT * NN];               // per-(type,dst) in-degree
__device__ int   g_off[NN];                    // exclusive CSR offsets (per dst)
__device__ int   g_cursor[NN];                 // fill cursors (end = off + deg)
__device__ int   g_epk[NE];                    // packed (src<<2)|type, bucketed by dst
__device__ int   g_bsum[64];                   // block sums for scan
__device__ __half g_Ah[(size_t)NN * F];        // fp16 activations
__device__ __half g_W1[NOUT * F];              // [n][k] layout (K-major rows)
__device__ __half g_W2[NOUT * F];
__device__ float g_bb1[F];
__device__ float g_bb2[F];

// ---------------- weight prep: fold type-mean, round to fp16 ----------------
__global__ void prep_weights(const float* __restrict__ Ws1, const float* __restrict__ Wn1,
                             const float* __restrict__ b1,
                             const float* __restrict__ Ws2, const float* __restrict__ Wn2,
                             const float* __restrict__ b2) {
    int idx = blockIdx.x * blockDim.x + threadIdx.x;   // over NOUT*F = 81920
    if (idx >= NOUT * F) return;
    int j = idx / F, k = idx % F;    // output col j, input k  (stored [j][k])
    float w1, w2;
    if (j < F) {
        float a1 = 0.f, a2 = 0.f;
        #pragma unroll
        for (int t = 0; t < NT; t++) {
            a1 += Ws1[(t * F + k) * F + j];
            a2 += Ws2[(t * F + k) * F + j];
        }
        w1 = a1 * 0.25f; w2 = a2 * 0.25f;
    } else {
        int t  = (j - F) >> 7;
        int jj = (j - F) & 127;
        w1 = Wn1[(t * F + k) * F + jj] * 0.25f;
        w2 = Wn2[(t * F + k) * F + jj] * 0.25f;
    }
    g_W1[idx] = __float2half_rn(w1);
    g_W2[idx] = __float2half_rn(w2);
    if (idx < F) {
        float s1 = 0.f, s2 = 0.f;
        #pragma unroll
        for (int t = 0; t < NT; t++) { s1 += b1[t * F + idx]; s2 += b2[t * F + idx]; }
        g_bb1[idx] = s1 * 0.25f; g_bb2[idx] = s2 * 0.25f;
    }
}

// ---------------- fp32 -> fp16 conversion (x only) ---------------------------
__global__ void convert_f16(const float* __restrict__ A) {
    size_t i = ((size_t)blockIdx.x * 256 + threadIdx.x) * 8;
    if (i >= (size_t)NN * F) return;
    float4 u0 = *reinterpret_cast<const float4*>(A + i);
    float4 u1 = *reinterpret_cast<const float4*>(A + i + 4);
    __half2 h0 = __floats2half2_rn(u0.x, u0.y);
    __half2 h1 = __floats2half2_rn(u0.z, u0.w);
    __half2 h2 = __floats2half2_rn(u1.x, u1.y);
    __half2 h3 = __floats2half2_rn(u1.z, u1.w);
    *reinterpret_cast<uint4*>(g_Ah + i) =
        make_uint4(*reinterpret_cast<uint32_t*>(&h0), *reinterpret_cast<uint32_t*>(&h1),
                   *reinterpret_cast<uint32_t*>(&h2), *reinterpret_cast<uint32_t*>(&h3));
}

// ---------------- CSR build ---------------------------------------------------
__global__ void zero_cnt() {
    int i = blockIdx.x * blockDim.x + threadIdx.x;
    if (i < NT * NN) g_cnt[i] = 0;
}
__global__ void count_edges(const int* __restrict__ ei, const int* __restrict__ et) {
    int e = blockIdx.x * blockDim.x + threadIdx.x;
    if (e >= NE) return;
    atomicAdd(&g_cnt[et[e] * NN + ei[NE + e]], 1);
}

__global__ void scan_blocks() {
    __shared__ int wsum[32];
    int tid = threadIdx.x, lane = tid & 31, w = tid >> 5;
    int idx = blockIdx.x * 1024 + tid;
    int v = 0;
    if (idx < NN) {
        #pragma unroll
        for (int t = 0; t < NT; t++) v += g_cnt[t * NN + idx];
    }
    int x = v;
    #pragma unroll
    for (int o = 1; o < 32; o <<= 1) {
        int y = __shfl_up_sync(0xFFFFFFFFu, x, o);
        if (lane >= o) x += y;
    }
    if (lane == 31) wsum[w] = x;
    __syncthreads();
    if (w == 0) {
        int s = wsum[lane];
        #pragma unroll
        for (int o = 1; o < 32; o <<= 1) {
            int y = __shfl_up_sync(0xFFFFFFFFu, s, o);
            if (lane >= o) s += y;
        }
        wsum[lane] = s;
    }
    __syncthreads();
    int excl = x - v + (w > 0 ? wsum[w - 1] : 0);
    if (idx < NN) g_off[idx] = excl;
    if (tid == 0) g_bsum[blockIdx.x] = wsum[31];
}
__global__ void scan_bsums() {
    __shared__ int s[64];
    int tid = threadIdx.x;
    s[tid] = (tid < 49) ? g_bsum[tid] : 0;
    __syncthreads();
    #pragma unroll
    for (int o = 1; o < 64; o <<= 1) {
        int v = (tid >= o) ? s[tid - o] : 0;
        __syncthreads();
        s[tid] += v;
        __syncthreads();
    }
    if (tid < 49) g_bsum[tid] = (tid > 0) ? s[tid - 1] : 0;
}
__global__ void add_bsums() {
    int idx = blockIdx.x * 1024 + threadIdx.x;
    if (idx < NN) {
        int o = g_off[idx] + g_bsum[blockIdx.x];
        g_off[idx] = o;
        g_cursor[idx] = o;
    }
}

__global__ void fill_edges(const int* __restrict__ ei, const int* __restrict__ et) {
    int e = blockIdx.x * blockDim.x + threadIdx.x;
    if (e >= NE) return;
    int src = ei[e];
    int dst = ei[NE + e];
    int t = et[e];
    int pos = atomicAdd(&g_cursor[dst], 1);
    g_epk[pos] = (src << 2) | t;
}

// ---------------- mma.sync fp16 GEMM: Y[N,640] = A[N,128] @ W[128,640] --------
// fp16 x fp16 -> f32 accum, fp16 store. One CTA (128 threads, 4 warps) per
// 128-row M tile; A resident; B streamed in 64-col halves, double-buffered.
__device__ __forceinline__ void mma_f32acc(float* d, const uint32_t* a, const uint32_t* b) {
    asm volatile("mma.sync.aligned.m16n8k16.row.col.f32.f16.f16.f32 "
                 "{%0,%1,%2,%3}, {%4,%5,%6,%7}, {%8,%9}, {%0,%1,%2,%3};"
                 : "+f"(d[0]), "+f"(d[1]), "+f"(d[2]), "+f"(d[3])
                 : "r"(a[0]), "r"(a[1]), "r"(a[2]), "r"(a[3]),
                   "r"(b[0]), "r"(b[1]));
}
__device__ __forceinline__ void ldsm_x4(uint32_t* r, uint32_t saddr) {
    asm volatile("ldmatrix.sync.aligned.m8n8.x4.shared.b16 {%0,%1,%2,%3}, [%4];"
                 : "=r"(r[0]), "=r"(r[1]), "=r"(r[2]), "=r"(r[3]) : "r"(saddr));
}
__device__ __forceinline__ void cp16(void* dst, const void* src) {
    uint32_t d = (uint32_t)__cvta_generic_to_shared(dst);
    asm volatile("cp.async.cg.shared.global [%0], [%1], 16;" :: "r"(d), "l"(src));
}
#define CP_COMMIT() asm volatile("cp.async.commit_group;" ::: "memory")
#define CP_WAIT(n)  asm volatile("cp.async.wait_group %0;" :: "n"(n) : "memory")

__global__ __launch_bounds__(128, 3)
void gemm_tc(const __half* __restrict__ wmat,
             const float* __restrict__ bias, __half* __restrict__ Y) {
    extern __shared__ __half smem[];
    __half* As   = smem;                             // 128 x RS
    __half* Bbuf = As + 128 * RS;                    // 2 x (64 x RS)

    int tid = threadIdx.x, wid = tid >> 5, lane = tid & 31;
    int gid = lane >> 2, tig = lane & 3;
    int l8 = lane & 7, sel = lane >> 3;
    int wm = wid & 1, wn = wid >> 1;                 // warp tile rows wm*64, cols wn*32
    int m0 = blockIdx.x * 128;

    // --- resident A tile, loaded once via cp.async (16 chunks/thread) ---
    {
        bool full = (m0 + 128 <= NN);
        #pragma unroll
        for (int i = 0; i < 16; i++) {
            int lin = tid + i * 128;                 // 0..2047
            int r = lin >> 4, c = lin & 15;
            int gr = m0 + r;
            if (full || gr < NN)
                cp16(As + r * RS + c * 8, g_Ah + (size_t)gr * F + c * 8);
            else
                *reinterpret_cast<uint4*>(As + r * RS + c * 8) = make_uint4(0, 0, 0, 0);
        }
    }
    // --- B half-tile prefetch into buffer buf ---
    auto issue_B = [&](int s, int buf) {
        const __half* src = wmat + (size_t)s * HALF_N * F;
        __half* dst = Bbuf + buf * HALF_N * RS;
        #pragma unroll
        for (int i = 0; i < 8; i++) {
            int lin = tid + i * 128;                 // 0..1023
            int r = lin >> 4, c = lin & 15;
            cp16(dst + r * RS + c * 8, src + r * F + c * 8);
        }
        CP_COMMIT();
    };
    issue_B(0, 0);

    uint32_t sA = (uint32_t)__cvta_generic_to_shared(As);

    int a_r = (sel & 1) * 8 + l8;
    int a_k = (sel >> 1) * 8;
    int b_n = (sel >> 1) * 8 + l8;
    int b_k = (sel & 1) * 8;

    for (int s = 0; s < NHALF; s++) {
        int buf = s & 1;
        if (s + 1 < NHALF) {
            issue_B(s + 1, buf ^ 1);
            CP_WAIT(1);
        } else {
            CP_WAIT(0);
        }
        __syncthreads();                              // B(s) + A visible

        uint32_t sB = (uint32_t)__cvta_generic_to_shared(Bbuf + buf * HALF_N * RS);

        float acc[4][4][4];
        #pragma unroll
        for (int i = 0; i < 4; i++)
            #pragma unroll
            for (int j = 0; j < 4; j++)
                #pragma unroll
                for (int q = 0; q < 4; q++) acc[i][j][q] = 0.f;

        #pragma unroll
        for (int ks = 0; ks < 8; ks++) {
            int kb = ks * 16;
            uint32_t af[4][4];
            #pragma unroll
            for (int mf = 0; mf < 4; mf++) {
                uint32_t off = (uint32_t)(((wm * 64 + mf * 16 + a_r) * RS + kb + a_k) * 2);
                ldsm_x4(af[mf], sA + off);
            }
            uint32_t bf[2][4];
            #pragma unroll
            for (int g = 0; g < 2; g++) {
                uint32_t off = (uint32_t)(((wn * 32 + g * 16 + b_n) * RS + kb + b_k) * 2);
                ldsm_x4(bf[g], sB + off);
            }
            #pragma unroll
            for (int mf = 0; mf < 4; mf++)
                #pragma unroll
                for (int g = 0; g < 2; g++) {
                    mma_f32acc(acc[mf][g * 2],     af[mf], &bf[g][0]);
                    mma_f32acc(acc[mf][g * 2 + 1], af[mf], &bf[g][2]);
                }
        }

        // epilogue for this 64-col half: global cols s*64 .. s*64+63, fp16 store
        int gc0 = s * HALF_N;
        bool has_bias = (gc0 < F);
        #pragma unroll
        for (int nf = 0; nf < 4; nf++) {
            int gc = gc0 + wn * 32 + nf * 8 + tig * 2;
            float b0 = has_bias ? bias[gc]     : 0.f;
            float b1 = has_bias ? bias[gc + 1] : 0.f;
            #pragma unroll
            for (int mf = 0; mf < 4; mf++) {
                int row = m0 + wm * 64 + mf * 16 + gid;
                __half* base = Y + (size_t)row * NOUT + gc;
                if (row < NN) {
                    __half2 p = __floats2half2_rn(acc[mf][nf][0] + b0, acc[mf][nf][1] + b1);
                    *reinterpret_cast<uint32_t*>(base) = *reinterpret_cast<uint32_t*>(&p);
                }
                if (row + 8 < NN) {
                    __half2 p = __floats2half2_rn(acc[mf][nf][2] + b0, acc[mf][nf][3] + b1);
                    *reinterpret_cast<uint32_t*>(base + 8 * NOUT) = *reinterpret_cast<uint32_t*>(&p);
                }
            }
        }
        __syncthreads();   // all warps done reading buf before it is refilled at s+2
    }
}

// ---------------- aggregate: out[dst] = Yself[dst] + sum_e invc[t]*Yt[src] ----
// Y is fp16; accumulation in fp32. NORM=true: l2norm+relu -> fp16 g_Ah.
__device__ __forceinline__ float4 ld_y4(const __half* p) {
    uint2 u = *reinterpret_cast<const uint2*>(p);
    float2 a = __half22float2(*reinterpret_cast<__half2*>(&u.x));
    float2 b = __half22float2(*reinterpret_cast<__half2*>(&u.y));
    return make_float4(a.x, a.y, b.x, b.y);
}

template <bool NORM>
__global__ void aggregate(float* __restrict__ outp) {
    int gtid = blockIdx.x * blockDim.x + threadIdx.x;
    int row = gtid >> 5;
    int lane = threadIdx.x & 31;
    if (row >= NN) return;

    float inv[NT];
    #pragma unroll
    for (int t = 0; t < NT; t++) {
        int c = __ldg(&g_cnt[t * NN + row]);
        inv[t] = 1.0f / (float)(c > 1 ? c : 1);
    }
    int beg = g_off[row];
    int end = g_cursor[row];

    float4 acc = ld_y4(g_Y + (size_t)row * NOUT + lane * 4);

    int i = beg;
    for (; i + 4 <= end; i += 4) {
        int pk0 = __ldg(&g_epk[i]);
        int pk1 = __ldg(&g_epk[i + 1]);
        int pk2 = __ldg(&g_epk[i + 2]);
        int pk3 = __ldg(&g_epk[i + 3]);
        float4 v0 = ld_y4(g_Y + (size_t)(pk0 >> 2) * NOUT + ((pk0 & 3) + 1) * F + lane * 4);
        float4 v1 = ld_y4(g_Y + (size_t)(pk1 >> 2) * NOUT + ((pk1 & 3) + 1) * F + lane * 4);
        float4 v2 = ld_y4(g_Y + (size_t)(pk2 >> 2) * NOUT + ((pk2 & 3) + 1) * F + lane * 4);
        float4 v3 = ld_y4(g_Y + (size_t)(pk3 >> 2) * NOUT + ((pk3 & 3) + 1) * F + lane * 4);
        float s0 = inv[pk0 & 3], s1 = inv[pk1 & 3], s2 = inv[pk2 & 3], s3 = inv[pk3 & 3];
        acc.x += s0 * v0.x; acc.y += s0 * v0.y; acc.z += s0 * v0.z; acc.w += s0 * v0.w;
        acc.x += s1 * v1.x; acc.y += s1 * v1.y; acc.z += s1 * v1.z; acc.w += s1 * v1.w;
        acc.x += s2 * v2.x; acc.y += s2 * v2.y; acc.z += s2 * v2.z; acc.w += s2 * v2.w;
        acc.x += s3 * v3.x; acc.y += s3 * v3.y; acc.z += s3 * v3.z; acc.w += s3 * v3.w;
    }
    for (; i < end; i++) {
        int pk = __ldg(&g_epk[i]);
        float4 v = ld_y4(g_Y + (size_t)(pk >> 2) * NOUT + ((pk & 3) + 1) * F + lane * 4);
        float s = inv[pk & 3];
        acc.x += s * v.x; acc.y += s * v.y; acc.z += s * v.z; acc.w += s * v.w;
    }

    if (NORM) {
        float ss = acc.x * acc.x + acc.y * acc.y + acc.z * acc.z + acc.w * acc.w;
        #pragma unroll
        for (int o = 16; o > 0; o >>= 1)
            ss += __shfl_xor_sync(0xFFFFFFFFu, ss, o);
        float invn = 1.0f / fmaxf(sqrtf(ss), 1e-12f);
        acc.x = fmaxf(acc.x * invn, 0.f);
        acc.y = fmaxf(acc.y * invn, 0.f);
        acc.z = fmaxf(acc.z * invn, 0.f);
        acc.w = fmaxf(acc.w * invn, 0.f);
        __half2 h0 = __floats2half2_rn(acc.x, acc.y);
        __half2 h1 = __floats2half2_rn(acc.z, acc.w);
        size_t o = (size_t)row * F + lane * 4;
        *reinterpret_cast<uint2*>(g_Ah + o) =
            make_uint2(*reinterpret_cast<uint32_t*>(&h0), *reinterpret_cast<uint32_t*>(&h1));
    } else {
        *(reinterpret_cast<float4*>(outp + (size_t)row * F) + lane) = acc;
    }
}

// ---------------- launch -------------------------------------------------------
extern "C" void kernel_launch(void* const* d_in, const int* in_sizes, int n_in,
                              void* d_out, int out_size) {
    const float* x   = (const float*)d_in[0];
    const float* Ws1 = (const float*)d_in[1];
    const float* Wn1 = (const float*)d_in[2];
    const float* b1  = (const float*)d_in[3];
    const float* Ws2 = (const float*)d_in[4];
    const float* Wn2 = (const float*)d_in[5];
    const float* b2  = (const float*)d_in[6];
    const int*   ei  = (const int*)d_in[7];
    const int*   et  = (const int*)d_in[8];
    float* out = (float*)d_out;

    void *p_Y, *p_bb1, *p_bb2, *p_W1, *p_W2;
    cudaGetSymbolAddress(&p_Y, g_Y);
    cudaGetSymbolAddress(&p_bb1, g_bb1);
    cudaGetSymbolAddress(&p_bb2, g_bb2);
    cudaGetSymbolAddress(&p_W1, g_W1);
    cudaGetSymbolAddress(&p_W2, g_W2);

    // smem: A (128*RS) + B double-buffered halves (2*64*RS) = 69.6KB -> 3 CTAs/SM
    const int SMEM_GEMM = (128 * RS + 2 * HALF_N * RS) * (int)sizeof(__half);
    cudaFuncSetAttribute(gemm_tc, cudaFuncAttributeMaxDynamicSharedMemorySize, SMEM_GEMM);

    const int GM_BLOCKS = (NN + 127) / 128;         // 391
    const int AG_BLOCKS = (int)(((size_t)NN * 32 + 255) / 256);
    const int SCAN_BLOCKS = (NN + 1023) / 1024;     // 49
    const int CV_BLOCKS = (int)(((size_t)NN * F / 8 + 255) / 256);

    // --- fork a side stream for the CSR build (independent of gemm1 path) ---
    cudaStream_t s2;
    cudaStreamCreateWithFlags(&s2, cudaStreamNonBlocking);
    cudaEvent_t evFork, evJoin;
    cudaEventCreateWithFlags(&evFork, cudaEventDisableTiming);
    cudaEventCreateWithFlags(&evJoin, cudaEventDisableTiming);

    cudaEventRecord(evFork, 0);
    cudaStreamWaitEvent(s2, evFork, 0);

    // main stream: weight prep + activation convert + layer-1 GEMM
    prep_weights<<<(NOUT * F + 255) / 256, 256>>>(Ws1, Wn1, b1, Ws2, Wn2, b2);
    convert_f16<<<CV_BLOCKS, 256>>>(x);
    gemm_tc<<<GM_BLOCKS, 128, SMEM_GEMM>>>((const __half*)p_W1,
                                           (const float*)p_bb1, (__half*)p_Y);

    // side stream: CSR build (runs concurrently with gemm1)
    zero_cnt<<<(NT * NN + 255) / 256, 256, 0, s2>>>();
    count_edges<<<(NE + 255) / 256, 256, 0, s2>>>(ei, et);
    scan_blocks<<<SCAN_BLOCKS, 1024, 0, s2>>>();
    scan_bsums<<<1, 64, 0, s2>>>();
    add_bsums<<<SCAN_BLOCKS, 1024, 0, s2>>>();
    fill_edges<<<(NE + 255) / 256, 256, 0, s2>>>(ei, et);

    cudaEventRecord(evJoin, s2);
    cudaStreamWaitEvent(0, evJoin, 0);

    // join: aggregate layer 1 needs both gemm1 (Y) and CSR
    aggregate<true><<<AG_BLOCKS, 256>>>(nullptr);    // writes g_Ah fp16

    // ---- layer 2 ----
    gemm_tc<<<GM_BLOCKS, 128, SMEM_GEMM>>>((const __half*)p_W2,
                                           (const float*)p_bb2, (__half*)p_Y);
    aggregate<false><<<AG_BLOCKS, 256>>>(out);

    cudaStreamDestroy(s2);
    cudaEventDestroy(evFork);
    cudaEventDestroy(evJoin);
}